// round 14
// baseline (speedup 1.0000x reference)
#include <cuda_runtime.h>
#include <cuda_bf16.h>
#include <math.h>
#include <stdint.h>

#define NUM_NODES 50000
#define NUM_EDGES 1600000
#define NUM_GRAPHS 128
#define HID 128
#define NUM_G 50
#define NUM_INTER 3
#define TBL 1024
#define WTOP 10.0f
#define WCUT 9.6f
#define LOG2F_ 0.6931471805599453f
#define PI_OVER_8 0.39269908169872414f
#define GCOEFF (-18.7578125f)
#define SCAN_N (NUM_NODES + 1)
#define SST 136
#define TILE_U4 (128 * 17)
#define NT64 ((NUM_NODES + 63) / 64)     /* 782  */
#define NT32 ((NUM_NODES + 31) / 32)     /* 1563 */

typedef unsigned long long u64;
typedef __nv_bfloat16 bf16;

// ---------------- static scratch ----------------
__device__ float  g_tval[NUM_INTER * TBL * HID];
__device__ uint4  g_tblb[NUM_INTER * TBL * 32];
__device__ uint4  g_wimg[9 * 2 * TILE_U4];
__device__ float4 g_pos4[NUM_NODES];
__device__ float  g_h[NUM_NODES * HID];
__device__ bf16   g_xb[NUM_NODES * HID];
__device__ float  g_agg[NUM_NODES * HID];
__device__ int4   g_epack[NUM_EDGES];
__device__ int2   g_esrc[NUM_EDGES];
__device__ int    g_deg[SCAN_N];
__device__ int    g_off[SCAN_N];
__device__ int    g_cur[NUM_NODES];
__device__ int    g_part[64];
__device__ float  g_sums[NUM_GRAPHS];
__device__ float  g_cnts[NUM_GRAPHS];

__device__ __forceinline__ float sspf(float v) {
    float sp = (v > 20.0f) ? v : log1pf(__expf(v));
    return sp - LOG2F_;
}
__device__ __forceinline__ float4 f4z() { return make_float4(0.f, 0.f, 0.f, 0.f); }

// ---------------- cp.async ----------------
#define CP_ASYNC16(saddr, gptr) \
    asm volatile("cp.async.ca.shared.global [%0], [%1], 16;" :: "r"(saddr), "l"(gptr) : "memory")
#define CP_COMMIT() asm volatile("cp.async.commit_group;" ::: "memory")
#define CP_WAIT(n)  asm volatile("cp.async.wait_group %0;" :: "n"(n) : "memory")

// ---------------- smem layouts ----------------
struct SmemXB {                      // gemm_xb: TM=64, 2 CTAs/SM (104448 B)
    bf16 Ah[64 * SST];
    bf16 Al[64 * SST];
    bf16 Wh[128 * SST];
    bf16 Wl[128 * SST];
};
struct SmemNU {                      // node_update: TM=32, 1 CTA/SM (226304 B)
    bf16 Ah[32 * SST];
    bf16 Al[32 * SST];
    bf16 W[6][128 * SST];            // {W2h,W2l, WLh,WLl, W1nh,W1nl}
};
#define SMEM_XB ((int)sizeof(SmemXB))
#define SMEM_NU ((int)sizeof(SmemNU))

__device__ __forceinline__ unsigned sptr(const void* p) {
    return (unsigned)__cvta_generic_to_shared(p);
}
__device__ __forceinline__ void ldsm4(uint32_t* r, unsigned addr) {
    asm volatile("ldmatrix.sync.aligned.m8n8.x4.shared.b16 {%0,%1,%2,%3}, [%4];"
                 : "=r"(r[0]), "=r"(r[1]), "=r"(r[2]), "=r"(r[3]) : "r"(addr));
}
__device__ __forceinline__ void ldsm4t(uint32_t* r, unsigned addr) {
    asm volatile("ldmatrix.sync.aligned.m8n8.x4.trans.shared.b16 {%0,%1,%2,%3}, [%4];"
                 : "=r"(r[0]), "=r"(r[1]), "=r"(r[2]), "=r"(r[3]) : "r"(addr));
}
__device__ __forceinline__ void mma16816(float* c, const uint32_t* a, uint32_t b0, uint32_t b1) {
    asm volatile("mma.sync.aligned.m16n8k16.row.col.f32.bf16.bf16.f32 "
                 "{%0,%1,%2,%3}, {%4,%5,%6,%7}, {%8,%9}, {%0,%1,%2,%3};"
                 : "+f"(c[0]), "+f"(c[1]), "+f"(c[2]), "+f"(c[3])
                 : "r"(a[0]), "r"(a[1]), "r"(a[2]), "r"(a[3]), "r"(b0), "r"(b1));
}

__device__ __forceinline__ void split_store(bf16* Ah, bf16* Al, int idx, float v0, float v1) {
    bf16 h0 = __float2bfloat16(v0), h1 = __float2bfloat16(v1);
    bf16 l0 = __float2bfloat16(v0 - __bfloat162float(h0));
    bf16 l1 = __float2bfloat16(v1 - __bfloat162float(h1));
    *reinterpret_cast<__nv_bfloat162*>(Ah + idx) = __halves2bfloat162(h0, h1);
    *reinterpret_cast<__nv_bfloat162*>(Al + idx) = __halves2bfloat162(l0, l1);
}

__device__ __forceinline__ void cp_w(bf16* Wh, bf16* Wl, const uint4* imgh, const uint4* imgl, int tid) {
#pragma unroll
    for (int i = 0; i < 8; i++) {
        int c = tid + i * 256;
        int r = c >> 4, g = c & 15;
        CP_ASYNC16(sptr(Wh + r * SST + g * 8), imgh + r * 17 + g);
        CP_ASYNC16(sptr(Wl + r * SST + g * 8), imgl + r * 17 + g);
    }
}

// ---- TM=64 mma (gemm_xb): warp = 32 rows x 32 cols, mb in {0,1}, nb in {0..3} ----
__device__ __forceinline__ void mma64(const bf16* Ah, const bf16* Al,
                                      const bf16* Wh, const bf16* Wl,
                                      float acc[2][4][4], int lane, int mb, int nb) {
#pragma unroll
    for (int mt = 0; mt < 2; mt++)
#pragma unroll
        for (int nt = 0; nt < 4; nt++)
#pragma unroll
            for (int q = 0; q < 4; q++) acc[mt][nt][q] = 0.f;
    int l15 = lane & 15, lq = (lane >> 4) * 8;
    int arow = mb * 32 + l15;
#pragma unroll
    for (int kc = 0; kc < 8; kc++) {
        uint32_t ah[2][4], al[2][4];
        ldsm4(ah[0], sptr(Ah + arow * SST + kc * 16 + lq));
        ldsm4(ah[1], sptr(Ah + (arow + 16) * SST + kc * 16 + lq));
        ldsm4(al[0], sptr(Al + arow * SST + kc * 16 + lq));
        ldsm4(al[1], sptr(Al + (arow + 16) * SST + kc * 16 + lq));
#pragma unroll
        for (int ntg = 0; ntg < 2; ntg++) {
            uint32_t bh[4], bl[4];
            unsigned wsoff = (kc * 16 + l15) * SST + nb * 32 + ntg * 16 + lq;
            ldsm4t(bh, sptr(Wh + wsoff));
            ldsm4t(bl, sptr(Wl + wsoff));
            float* c0 = acc[0][ntg * 2];
            float* c1 = acc[0][ntg * 2 + 1];
            float* c2 = acc[1][ntg * 2];
            float* c3 = acc[1][ntg * 2 + 1];
            mma16816(c0, ah[0], bh[0], bh[1]); mma16816(c1, ah[0], bh[2], bh[3]);
            mma16816(c2, ah[1], bh[0], bh[1]); mma16816(c3, ah[1], bh[2], bh[3]);
            mma16816(c0, al[0], bh[0], bh[1]); mma16816(c1, al[0], bh[2], bh[3]);
            mma16816(c2, al[1], bh[0], bh[1]); mma16816(c3, al[1], bh[2], bh[3]);
            mma16816(c0, ah[0], bl[0], bl[1]); mma16816(c1, ah[0], bl[2], bl[3]);
            mma16816(c2, ah[1], bl[0], bl[1]); mma16816(c3, ah[1], bl[2], bl[3]);
        }
    }
}

// ---- TM=32 mma (node_update): warp = 32 rows x 16 cols, nb = wid in {0..7} ----
__device__ __forceinline__ void mma32(const bf16* Ah, const bf16* Al,
                                      const bf16* Wh, const bf16* Wl,
                                      float acc[2][2][4], int lane, int nb) {
#pragma unroll
    for (int mt = 0; mt < 2; mt++)
#pragma unroll
        for (int nt = 0; nt < 2; nt++)
#pragma unroll
            for (int q = 0; q < 4; q++) acc[mt][nt][q] = 0.f;
    int l15 = lane & 15, lq = (lane >> 4) * 8;
#pragma unroll
    for (int kc = 0; kc < 8; kc++) {
        uint32_t ah[2][4], al[2][4];
        ldsm4(ah[0], sptr(Ah + l15 * SST + kc * 16 + lq));
        ldsm4(ah[1], sptr(Ah + (l15 + 16) * SST + kc * 16 + lq));
        ldsm4(al[0], sptr(Al + l15 * SST + kc * 16 + lq));
        ldsm4(al[1], sptr(Al + (l15 + 16) * SST + kc * 16 + lq));
        uint32_t bh[4], bl[4];
        unsigned wsoff = (kc * 16 + l15) * SST + nb * 16 + lq;
        ldsm4t(bh, sptr(Wh + wsoff));
        ldsm4t(bl, sptr(Wl + wsoff));
        float* c0 = acc[0][0];
        float* c1 = acc[0][1];
        float* c2 = acc[1][0];
        float* c3 = acc[1][1];
        mma16816(c0, ah[0], bh[0], bh[1]); mma16816(c1, ah[0], bh[2], bh[3]);
        mma16816(c2, ah[1], bh[0], bh[1]); mma16816(c3, ah[1], bh[2], bh[3]);
        mma16816(c0, al[0], bh[0], bh[1]); mma16816(c1, al[0], bh[2], bh[3]);
        mma16816(c2, al[1], bh[0], bh[1]); mma16816(c3, al[1], bh[2], bh[3]);
        mma16816(c0, ah[0], bl[0], bl[1]); mma16816(c1, ah[0], bl[2], bl[3]);
        mma16816(c2, ah[1], bl[0], bl[1]); mma16816(c3, ah[1], bl[2], bl[3]);
    }
}

// ---------------- weight image prep ----------------
__global__ void prep_w(const float* __restrict__ cf_w1,
                       const float* __restrict__ cf_w2,
                       const float* __restrict__ lin_w) {
    int m = blockIdx.x;
    const float* W = (m < 3) ? cf_w1 + (size_t)m * HID * HID
                   : (m < 6) ? cf_w2 + (size_t)(m - 3) * HID * HID
                             : lin_w + (size_t)(m - 6) * HID * HID;
    uint4* imgh = g_wimg + (size_t)m * 2 * TILE_U4;
    uint4* imgl = imgh + TILE_U4;
    int tid = threadIdx.x;
#pragma unroll
    for (int i = 0; i < 8; i++) {
        int c = tid + i * 256;
        int r = c >> 4, g = c & 15;
        const float4* src = reinterpret_cast<const float4*>(W + (size_t)r * HID + g * 8);
        float4 v0 = __ldg(src), v1 = __ldg(src + 1);
        float vv[8] = {v0.x, v0.y, v0.z, v0.w, v1.x, v1.y, v1.z, v1.w};
        unsigned ph[4], pl[4];
#pragma unroll
        for (int e = 0; e < 4; e++) {
            bf16 h0 = __float2bfloat16(vv[2 * e]);
            bf16 h1 = __float2bfloat16(vv[2 * e + 1]);
            bf16 l0 = __float2bfloat16(vv[2 * e] - __bfloat162float(h0));
            bf16 l1 = __float2bfloat16(vv[2 * e + 1] - __bfloat162float(h1));
            __nv_bfloat162 hp = __halves2bfloat162(h0, h1);
            __nv_bfloat162 lp = __halves2bfloat162(l0, l1);
            ph[e] = *reinterpret_cast<unsigned*>(&hp);
            pl[e] = *reinterpret_cast<unsigned*>(&lp);
        }
        imgh[r * 17 + g] = make_uint4(ph[0], ph[1], ph[2], ph[3]);
        imgl[r * 17 + g] = make_uint4(pl[0], pl[1], pl[2], pl[3]);
    }
}

// ---------------- persistent init + first GEMM (TM=64, 2 CTA/SM) ----------------
__global__ void __launch_bounds__(256, 2) gemm_xb(const float* __restrict__ emb,
                                                  const int* __restrict__ z) {
    extern __shared__ char smraw[];
    SmemXB& sm = *reinterpret_cast<SmemXB*>(smraw);
    int tid = threadIdx.x, lane = tid & 31, wid = tid >> 5;
    int mb = wid & 1, nb = wid >> 1;

    cp_w(sm.Wh, sm.Wl, g_wimg, g_wimg + TILE_U4, tid);
    CP_COMMIT();

    int t = blockIdx.x;
    // stage first A tile (overlaps W copy)
    if (t < NT64) {
        int row0 = t * 64;
        int r = tid >> 2, c0 = (tid & 3) * 32;
        int gr = row0 + r;
        bool ok = gr < NUM_NODES;
        int zz = ok ? __ldg(z + gr) : 0;
        const float4* src = reinterpret_cast<const float4*>(emb + (size_t)zz * HID + c0);
        float4* hdst = reinterpret_cast<float4*>(g_h + (size_t)gr * HID + c0);
#pragma unroll
        for (int q = 0; q < 8; q++) {
            float4 v = ok ? __ldg(src + q) : f4z();
            if (ok) hdst[q] = v;
            int base = r * SST + c0 + q * 4;
            split_store(sm.Ah, sm.Al, base, v.x, v.y);
            split_store(sm.Ah, sm.Al, base + 2, v.z, v.w);
        }
    }
    CP_WAIT(0);
    __syncthreads();

    while (t < NT64) {
        int row0 = t * 64;
        float acc[2][4][4];
        mma64(sm.Ah, sm.Al, sm.Wh, sm.Wl, acc, lane, mb, nb);
        // epilogue: xb = D (bf16)
#pragma unroll
        for (int mt = 0; mt < 2; mt++) {
            int rl = mb * 32 + mt * 16 + (lane >> 2);
#pragma unroll
            for (int nt = 0; nt < 4; nt++) {
                int col = nb * 32 + nt * 8 + (lane & 3) * 2;
                int r0 = row0 + rl, r1 = r0 + 8;
                if (r0 < NUM_NODES)
                    *reinterpret_cast<__nv_bfloat162*>(g_xb + (size_t)r0 * HID + col) =
                        __floats2bfloat162_rn(acc[mt][nt][0], acc[mt][nt][1]);
                if (r1 < NUM_NODES)
                    *reinterpret_cast<__nv_bfloat162*>(g_xb + (size_t)r1 * HID + col) =
                        __floats2bfloat162_rn(acc[mt][nt][2], acc[mt][nt][3]);
            }
        }
        int tn = t + gridDim.x;
        __syncthreads();           // everyone done reading A
        if (tn < NT64) {
            int row0n = tn * 64;
            int r = tid >> 2, c0 = (tid & 3) * 32;
            int gr = row0n + r;
            bool ok = gr < NUM_NODES;
            int zz = ok ? __ldg(z + gr) : 0;
            const float4* src = reinterpret_cast<const float4*>(emb + (size_t)zz * HID + c0);
            float4* hdst = reinterpret_cast<float4*>(g_h + (size_t)gr * HID + c0);
#pragma unroll
            for (int q = 0; q < 8; q++) {
                float4 v = ok ? __ldg(src + q) : f4z();
                if (ok) hdst[q] = v;
                int base = r * SST + c0 + q * 4;
                split_store(sm.Ah, sm.Al, base, v.x, v.y);
                split_store(sm.Ah, sm.Al, base + 2, v.z, v.w);
            }
            __syncthreads();
        }
        t = tn;
    }
}

// ---------------- persistent fused node update (TM=32, 1 CTA/SM) ----------------
template <int LAST>
__global__ void __launch_bounds__(256, 1) node_update(int mW2, int mWL, int mW1n,
                                                      const float* __restrict__ b2,
                                                      const float* __restrict__ bL) {
    extern __shared__ char smraw[];
    SmemNU& sm = *reinterpret_cast<SmemNU*>(smraw);
    int tid = threadIdx.x, lane = tid & 31, nb = tid >> 5;

    const uint4* i2 = g_wimg + (size_t)mW2 * 2 * TILE_U4;
    const uint4* iL = g_wimg + (size_t)mWL * 2 * TILE_U4;
    cp_w(sm.W[0], sm.W[1], i2, i2 + TILE_U4, tid);
    cp_w(sm.W[2], sm.W[3], iL, iL + TILE_U4, tid);
    if (!LAST) {
        const uint4* iN = g_wimg + (size_t)mW1n * 2 * TILE_U4;
        cp_w(sm.W[4], sm.W[5], iN, iN + TILE_U4, tid);
    }
    CP_COMMIT();
    CP_WAIT(0);
    __syncthreads();

    float acc[2][2][4];
    for (int t = blockIdx.x; t < NT32; t += gridDim.x) {
        int row0 = t * 32;
        // stage A = agg tile
        {
            int r = tid >> 3, c0 = (tid & 7) * 16;
            bool ok = (row0 + r) < NUM_NODES;
            const float4* src = reinterpret_cast<const float4*>(g_agg + (size_t)(row0 + r) * HID + c0);
#pragma unroll
            for (int q = 0; q < 4; q++) {
                float4 v = ok ? __ldg(src + q) : f4z();
                int base = r * SST + c0 + q * 4;
                split_store(sm.Ah, sm.Al, base, v.x, v.y);
                split_store(sm.Ah, sm.Al, base + 2, v.z, v.w);
            }
        }
        __syncthreads();

        // ---- pass A: agg @ W2 ----
        mma32(sm.Ah, sm.Al, sm.W[0], sm.W[1], acc, lane, nb);
        __syncthreads();
        // epilogue A: Us = ssp(D + b2) -> Ah/Al
#pragma unroll
        for (int mt = 0; mt < 2; mt++) {
            int rl = mt * 16 + (lane >> 2);
#pragma unroll
            for (int nt = 0; nt < 2; nt++) {
                int col = nb * 16 + nt * 8 + (lane & 3) * 2;
                float bb0 = __ldg(b2 + col), bb1 = __ldg(b2 + col + 1);
                split_store(sm.Ah, sm.Al, rl * SST + col,
                            sspf(acc[mt][nt][0] + bb0), sspf(acc[mt][nt][1] + bb1));
                split_store(sm.Ah, sm.Al, (rl + 8) * SST + col,
                            sspf(acc[mt][nt][2] + bb0), sspf(acc[mt][nt][3] + bb1));
            }
        }
        __syncthreads();

        // ---- pass B: Us @ WL ----
        mma32(sm.Ah, sm.Al, sm.W[2], sm.W[3], acc, lane, nb);
        __syncthreads();
        // epilogue B: h += D + bL ; stage h_new
#pragma unroll
        for (int mt = 0; mt < 2; mt++) {
            int rl = mt * 16 + (lane >> 2);
#pragma unroll
            for (int nt = 0; nt < 2; nt++) {
                int col = nb * 16 + nt * 8 + (lane & 3) * 2;
                float bb0 = __ldg(bL + col), bb1 = __ldg(bL + col + 1);
#pragma unroll
                for (int half = 0; half < 2; half++) {
                    int r = row0 + rl + half * 8;
                    bool ok = r < NUM_NODES;
                    float2 hv = ok ? *reinterpret_cast<const float2*>(g_h + (size_t)r * HID + col)
                                   : make_float2(0.f, 0.f);
                    float v0 = hv.x + acc[mt][nt][half * 2] + bb0;
                    float v1 = hv.y + acc[mt][nt][half * 2 + 1] + bb1;
                    if (ok)
                        *reinterpret_cast<float2*>(g_h + (size_t)r * HID + col) = make_float2(v0, v1);
                    if (!LAST)
                        split_store(sm.Ah, sm.Al, (rl + half * 8) * SST + col, v0, v1);
                }
            }
        }
        if (!LAST) {
            __syncthreads();
            // ---- pass C: xb = h_new @ W1n ----
            mma32(sm.Ah, sm.Al, sm.W[4], sm.W[5], acc, lane, nb);
#pragma unroll
            for (int mt = 0; mt < 2; mt++) {
                int rl = mt * 16 + (lane >> 2);
#pragma unroll
                for (int nt = 0; nt < 2; nt++) {
                    int col = nb * 16 + nt * 8 + (lane & 3) * 2;
                    int r0 = row0 + rl, r1 = r0 + 8;
                    if (r0 < NUM_NODES)
                        *reinterpret_cast<__nv_bfloat162*>(g_xb + (size_t)r0 * HID + col) =
                            __floats2bfloat162_rn(acc[mt][nt][0], acc[mt][nt][1]);
                    if (r1 < NUM_NODES)
                        *reinterpret_cast<__nv_bfloat162*>(g_xb + (size_t)r1 * HID + col) =
                            __floats2bfloat162_rn(acc[mt][nt][2], acc[mt][nt][3]);
                }
            }
        }
        __syncthreads();   // before next tile overwrites A
    }
}

// ---------------- setup kernels ----------------
__global__ void zero_meta() {
    int i = blockIdx.x * blockDim.x + threadIdx.x;
    if (i < SCAN_N) g_deg[i] = 0;
}

__global__ void prep_pos4(const float* __restrict__ pos) {
    int n = blockIdx.x * blockDim.x + threadIdx.x;
    if (n >= NUM_NODES) return;
    g_pos4[n] = make_float4(__ldg(pos + n * 3), __ldg(pos + n * 3 + 1),
                            __ldg(pos + n * 3 + 2), 0.f);
}

__global__ void prep_edges(const float* __restrict__ shift,
                           const int* __restrict__ ei) {
    int e = blockIdx.x * blockDim.x + threadIdx.x;
    if (e >= NUM_EDGES) return;
    int s = __ldg(ei + e);
    int d = __ldg(ei + NUM_EDGES + e);
    float4 ps = __ldg(&g_pos4[s]);
    float4 pd = __ldg(&g_pos4[d]);
    float sx = __ldg(shift + e * 3 + 0);
    float sy = __ldg(shift + e * 3 + 1);
    float sz = __ldg(shift + e * 3 + 2);
    float dx = ps.x - pd.x - sx;
    float dy = ps.y - pd.y - sy;
    float dz = ps.z - pd.z - sz;
    float w = sqrtf(dx * dx + dy * dy + dz * dz);
    float t = -1.0f;
    if (w < WCUT) {
        t = w * ((float)(TBL - 1) / WTOP);
        atomicAdd(&g_deg[d + 1], 1);
    }
    g_epack[e] = make_int4(s, d, __float_as_int(t), 0);
}

__device__ __forceinline__ int blk_incl_scan(int v, int tid, int* warp_sums) {
    int x = v;
#pragma unroll
    for (int o = 1; o < 32; o <<= 1) {
        int y = __shfl_up_sync(0xffffffffu, x, o);
        if ((tid & 31) >= o) x += y;
    }
    if ((tid & 31) == 31) warp_sums[tid >> 5] = x;
    __syncthreads();
    if (tid < 32) {
        int s = warp_sums[tid];
#pragma unroll
        for (int o = 1; o < 32; o <<= 1) {
            int y = __shfl_up_sync(0xffffffffu, s, o);
            if (tid >= o) s += y;
        }
        warp_sums[tid] = s;
    }
    __syncthreads();
    return x + ((tid >= 32) ? warp_sums[(tid >> 5) - 1] : 0);
}

__global__ void scan_block() {
    __shared__ int ws[32];
    int tid = threadIdx.x;
    int gid = blockIdx.x * 1024 + tid;
    int v = (gid < SCAN_N) ? g_deg[gid] : 0;
    int incl = blk_incl_scan(v, tid, ws);
    if (gid < SCAN_N) g_off[gid] = incl;
    if (tid == 1023) g_part[blockIdx.x] = incl;
}

__global__ void scan_part() {
    __shared__ int ws[32];
    int tid = threadIdx.x;
    int v = (tid < 49) ? g_part[tid] : 0;
    int incl = blk_incl_scan(v, tid, ws);
    if (tid < 64) g_part[tid] = incl - v;
    if (tid < NUM_GRAPHS) { g_sums[tid] = 0.f; g_cnts[tid] = 0.f; }
}

__global__ void scan_add() {
    int tid = threadIdx.x;
    int gid = blockIdx.x * 1024 + tid;
    if (gid >= SCAN_N) return;
    int val = g_off[gid] + g_part[blockIdx.x];
    g_off[gid] = val;
    if (gid < NUM_NODES) g_cur[gid] = val;
}

__global__ void scatter_csr() {
    int e = blockIdx.x * blockDim.x + threadIdx.x;
    if (e >= NUM_EDGES) return;
    int4 pk = __ldg(&g_epack[e]);
    if (__int_as_float(pk.z) < 0.f) return;
    int pos = atomicAdd(&g_cur[pk.y], 1);
    g_esrc[pos] = make_int2(pk.x, pk.z);
}

// ---------------- Wf(w) table ----------------
__global__ void build_val(const float* __restrict__ w1, const float* __restrict__ b1,
                          const float* __restrict__ w2, const float* __restrict__ b2) {
    int j = blockIdx.x, it = blockIdx.y, tid = threadIdx.x;
    __shared__ float attr[NUM_G];
    __shared__ float act[HID];
    float w = (float)j * (WTOP / (float)(TBL - 1));
    if (tid < NUM_G) {
        float off = (float)tid * (8.0f / 49.0f);
        float dlt = w - off;
        attr[tid] = __expf(GCOEFF * dlt * dlt);
    }
    __syncthreads();
    const float* W1 = w1 + it * NUM_G * HID;
    float u = b1[it * HID + tid];
#pragma unroll
    for (int g = 0; g < NUM_G; g++) u += attr[g] * W1[g * HID + tid];
    act[tid] = sspf(u);
    __syncthreads();
    const float* W2 = w2 + it * HID * HID;
    float v = b2[it * HID + tid];
#pragma unroll 8
    for (int k = 0; k < HID; k++) v += act[k] * W2[k * HID + tid];
    float C = 0.5f * (cosf(w * PI_OVER_8) + 1.0f);
    g_tval[(size_t)(it * TBL + j) * HID + tid] = v * C;
}

__global__ void build_pack() {
    int j = blockIdx.x, it = blockIdx.y, t = threadIdx.x;
    size_t row = (size_t)(it * TBL + j) * HID;
    float v0 = g_tval[row + 2 * t];
    float v1 = g_tval[row + 2 * t + 1];
    float n0 = v0, n1 = v1;
    if (j < TBL - 1) {
        n0 = g_tval[row + HID + 2 * t];
        n1 = g_tval[row + HID + 2 * t + 1];
    }
    __nv_bfloat162 vv = __floats2bfloat162_rn(v0, v1);
    __nv_bfloat162 ss = __floats2bfloat162_rn(n0 - v0, n1 - v1);
    uint2 pk = make_uint2(*reinterpret_cast<unsigned*>(&vv),
                          *reinterpret_cast<unsigned*>(&ss));
    reinterpret_cast<uint2*>(g_tblb)[((size_t)(it * TBL + j) * 64) + t] = pk;
}

// ---------------- gather: warp per node ----------------
__global__ void gather(const uint4* __restrict__ tbl) {
    int n = (blockIdx.x * blockDim.x + threadIdx.x) >> 5;
    if (n >= NUM_NODES) return;
    int lane = threadIdx.x & 31;
    int beg = __ldg(&g_off[n]);
    int end = __ldg(&g_off[n + 1]);
    float4 acc = f4z();
#pragma unroll 4
    for (int e = beg; e < end; e++) {
        int2 p = __ldg(&g_esrc[e]);
        float t = __int_as_float(p.y);
        int bin = (int)t;
        float f = t - (float)bin;
        uint4 tv = __ldg(tbl + (size_t)bin * 32 + lane);
        float2 v01 = __bfloat1622float2(*reinterpret_cast<__nv_bfloat162*>(&tv.x));
        float2 s01 = __bfloat1622float2(*reinterpret_cast<__nv_bfloat162*>(&tv.y));
        float2 v23 = __bfloat1622float2(*reinterpret_cast<__nv_bfloat162*>(&tv.z));
        float2 s23 = __bfloat1622float2(*reinterpret_cast<__nv_bfloat162*>(&tv.w));
        uint2 xb = __ldg(reinterpret_cast<const uint2*>(g_xb + (size_t)p.x * HID) + lane);
        float2 x01 = __bfloat1622float2(*reinterpret_cast<__nv_bfloat162*>(&xb.x));
        float2 x23 = __bfloat1622float2(*reinterpret_cast<__nv_bfloat162*>(&xb.y));
        acc.x = fmaf(x01.x, fmaf(f, s01.x, v01.x), acc.x);
        acc.y = fmaf(x01.y, fmaf(f, s01.y, v01.y), acc.y);
        acc.z = fmaf(x23.x, fmaf(f, s23.x, v23.x), acc.z);
        acc.w = fmaf(x23.y, fmaf(f, s23.y, v23.y), acc.w);
    }
    *reinterpret_cast<float4*>(g_agg + (size_t)n * HID + lane * 4) = acc;
}

// ---------------- readout ----------------
__global__ void head_kernel(const float* __restrict__ hw1, const float* __restrict__ hb1,
                            const float* __restrict__ hw2, const float* __restrict__ hb2,
                            const int* __restrict__ batch) {
    int n = (blockIdx.x * blockDim.x + threadIdx.x) >> 5;
    if (n >= NUM_NODES) return;
    int lane = threadIdx.x & 31;
    const float* hrow = g_h + (size_t)n * HID;
    float hr[4];
#pragma unroll
    for (int q = 0; q < 4; q++) hr[q] = hrow[q * 32 + lane];
    float u0 = hb1[lane];
    float u1 = hb1[lane + 32];
#pragma unroll
    for (int k = 0; k < HID; k++) {
        float hv = __shfl_sync(0xffffffffu, hr[k >> 5], k & 31);
        u0 = fmaf(hv, hw1[k * 64 + lane], u0);
        u1 = fmaf(hv, hw1[k * 64 + lane + 32], u1);
    }
    float part = sspf(u0) * hw2[lane] + sspf(u1) * hw2[lane + 32];
#pragma unroll
    for (int o = 16; o; o >>= 1) part += __shfl_down_sync(0xffffffffu, part, o);
    if (lane == 0) {
        int b = batch[n];
        atomicAdd(&g_sums[b], part + hb2[0]);
        atomicAdd(&g_cnts[b], 1.0f);
    }
}

__global__ void finalize(float* __restrict__ out) {
    int g = threadIdx.x;
    if (g < NUM_GRAPHS) out[g] = g_sums[g] / fmaxf(g_cnts[g], 1.0f);
}

// ---------------- launcher ----------------
extern "C" void kernel_launch(void* const* d_in, const int* in_sizes, int n_in,
                              void* d_out, int out_size) {
    const float* pos    = (const float*)d_in[0];
    const float* shift  = (const float*)d_in[1];
    const float* emb    = (const float*)d_in[2];
    const float* mlp_w1 = (const float*)d_in[3];
    const float* mlp_b1 = (const float*)d_in[4];
    const float* mlp_w2 = (const float*)d_in[5];
    const float* mlp_b2 = (const float*)d_in[6];
    const float* cf_w1  = (const float*)d_in[7];
    const float* cf_w2  = (const float*)d_in[8];
    const float* cf_b2  = (const float*)d_in[9];
    const float* lin_w  = (const float*)d_in[10];
    const float* lin_b  = (const float*)d_in[11];
    const float* hw1    = (const float*)d_in[12];
    const float* hb1    = (const float*)d_in[13];
    const float* hw2    = (const float*)d_in[14];
    const float* hb2    = (const float*)d_in[15];
    const int*   z      = (const int*)d_in[16];
    const int*   ei     = (const int*)d_in[17];
    const int*   batch  = (const int*)d_in[18];
    float* out = (float*)d_out;

    uint4* tblb_p;
    cudaGetSymbolAddress((void**)&tblb_p, g_tblb);

    cudaFuncSetAttribute(gemm_xb,        cudaFuncAttributeMaxDynamicSharedMemorySize, SMEM_XB);
    cudaFuncSetAttribute(node_update<0>, cudaFuncAttributeMaxDynamicSharedMemorySize, SMEM_NU);
    cudaFuncSetAttribute(node_update<1>, cudaFuncAttributeMaxDynamicSharedMemorySize, SMEM_NU);

    int sgrid = (SCAN_N + 1023) / 1024;
    dim3 tgrid(TBL, NUM_INTER);

    zero_meta<<<sgrid, 1024>>>();
    prep_w<<<9, 256>>>(cf_w1, cf_w2, lin_w);
    prep_pos4<<<(NUM_NODES + 255) / 256, 256>>>(pos);
    gemm_xb<<<296, 256, SMEM_XB>>>(emb, z);                         // profiled slot
    build_val<<<tgrid, 128>>>(mlp_w1, mlp_b1, mlp_w2, mlp_b2);
    build_pack<<<tgrid, 64>>>();
    prep_edges<<<(NUM_EDGES + 255) / 256, 256>>>(shift, ei);
    scan_block<<<sgrid, 1024>>>();
    scan_part<<<1, 1024>>>();
    scan_add<<<sgrid, 1024>>>();
    scatter_csr<<<(NUM_EDGES + 255) / 256, 256>>>();

    int wgrid = (int)(((long long)NUM_NODES * 32 + 255) / 256);
    for (int i = 0; i < NUM_INTER; i++) {
        gather<<<wgrid, 256>>>(tblb_p + (size_t)i * TBL * 32);
        const float* b2p = cf_b2 + (size_t)i * HID;
        const float* bLp = lin_b + (size_t)i * HID;
        if (i < NUM_INTER - 1) {
            node_update<0><<<148, 256, SMEM_NU>>>(3 + i, 6 + i, i + 1, b2p, bLp);
        } else {
            node_update<1><<<148, 256, SMEM_NU>>>(3 + i, 6 + i, 0, b2p, bLp);
        }
    }

    head_kernel<<<wgrid, 256>>>(hw1, hb1, hw2, hb2, batch);
    finalize<<<1, 128>>>(out);
}

// round 15
// speedup vs baseline: 1.0690x; 1.0690x over previous
#include <cuda_runtime.h>
#include <cuda_bf16.h>
#include <math.h>
#include <stdint.h>

#define NUM_NODES 50000
#define NUM_EDGES 1600000
#define NUM_GRAPHS 128
#define HID 128
#define NUM_G 50
#define NUM_INTER 3
#define TBL 1024
#define WTOP 10.0f
#define WCUT 9.6f
#define LOG2F_ 0.6931471805599453f
#define PI_OVER_8 0.39269908169872414f
#define GCOEFF (-18.7578125f)
#define SCAN_N (NUM_NODES + 1)
#define SST 136
#define TM 64
#define TILE_U4 (128 * 17)
#define NT64 ((NUM_NODES + 63) / 64)

typedef unsigned long long u64;
typedef __nv_bfloat16 bf16;

// ---------------- static scratch ----------------
__device__ float  g_tval[NUM_INTER * TBL * HID];
__device__ uint4  g_tblb[NUM_INTER * TBL * 32];
__device__ uint4  g_wimg[9 * 2 * TILE_U4];
__device__ float4 g_pos4[NUM_NODES];
__device__ float  g_h[NUM_NODES * HID];
__device__ bf16   g_xb[NUM_NODES * HID];
__device__ float  g_agg[NUM_NODES * HID];
__device__ int4   g_epack[NUM_EDGES];
__device__ int2   g_esrc[NUM_EDGES];
__device__ int    g_deg[SCAN_N];
__device__ int    g_off[SCAN_N];
__device__ int    g_cur[NUM_NODES];
__device__ int    g_part[64];
__device__ float  g_sums[NUM_GRAPHS];
__device__ float  g_cnts[NUM_GRAPHS];

__device__ __forceinline__ float sspf(float v) {
    float sp = (v > 20.0f) ? v : log1pf(__expf(v));
    return sp - LOG2F_;
}
__device__ __forceinline__ float4 f4z() { return make_float4(0.f, 0.f, 0.f, 0.f); }

// ---------------- cp.async ----------------
#define CP_ASYNC16(saddr, gptr) \
    asm volatile("cp.async.ca.shared.global [%0], [%1], 16;" :: "r"(saddr), "l"(gptr) : "memory")
#define CP_COMMIT() asm volatile("cp.async.commit_group;" ::: "memory")
#define CP_WAIT(n)  asm volatile("cp.async.wait_group %0;" :: "n"(n) : "memory")

// ---------------- MMA smem ----------------
struct SmemMMA {
    bf16 Ah[TM * SST];
    bf16 Al[TM * SST];
    bf16 Wh[128 * SST];
    bf16 Wl[128 * SST];
};
#define SMEM_MMA ((int)sizeof(SmemMMA))

__device__ __forceinline__ unsigned sptr(const void* p) {
    return (unsigned)__cvta_generic_to_shared(p);
}
__device__ __forceinline__ void ldsm4(uint32_t* r, unsigned addr) {
    asm volatile("ldmatrix.sync.aligned.m8n8.x4.shared.b16 {%0,%1,%2,%3}, [%4];"
                 : "=r"(r[0]), "=r"(r[1]), "=r"(r[2]), "=r"(r[3]) : "r"(addr));
}
__device__ __forceinline__ void ldsm4t(uint32_t* r, unsigned addr) {
    asm volatile("ldmatrix.sync.aligned.m8n8.x4.trans.shared.b16 {%0,%1,%2,%3}, [%4];"
                 : "=r"(r[0]), "=r"(r[1]), "=r"(r[2]), "=r"(r[3]) : "r"(addr));
}
__device__ __forceinline__ void mma16816(float* c, const uint32_t* a, uint32_t b0, uint32_t b1) {
    asm volatile("mma.sync.aligned.m16n8k16.row.col.f32.bf16.bf16.f32 "
                 "{%0,%1,%2,%3}, {%4,%5,%6,%7}, {%8,%9}, {%0,%1,%2,%3};"
                 : "+f"(c[0]), "+f"(c[1]), "+f"(c[2]), "+f"(c[3])
                 : "r"(a[0]), "r"(a[1]), "r"(a[2]), "r"(a[3]), "r"(b0), "r"(b1));
}

__device__ __forceinline__ void split_store(bf16* Ah, bf16* Al, int idx, float v0, float v1) {
    bf16 h0 = __float2bfloat16(v0), h1 = __float2bfloat16(v1);
    bf16 l0 = __float2bfloat16(v0 - __bfloat162float(h0));
    bf16 l1 = __float2bfloat16(v1 - __bfloat162float(h1));
    *reinterpret_cast<__nv_bfloat162*>(Ah + idx) = __halves2bfloat162(h0, h1);
    *reinterpret_cast<__nv_bfloat162*>(Al + idx) = __halves2bfloat162(l0, l1);
}

__device__ __forceinline__ void load_splitA(const float* __restrict__ Ag, int row0,
                                            bf16* Ah, bf16* Al, int tid) {
    int r = tid >> 2, c0 = (tid & 3) * 32;
    bool ok = (row0 + r) < NUM_NODES;
    const float4* src = reinterpret_cast<const float4*>(Ag + (size_t)(row0 + r) * HID + c0);
#pragma unroll
    for (int q = 0; q < 8; q++) {
        float4 v = ok ? __ldg(src + q) : f4z();
        int base = r * SST + c0 + q * 4;
        split_store(Ah, Al, base, v.x, v.y);
        split_store(Ah, Al, base + 2, v.z, v.w);
    }
}

__device__ __forceinline__ void cp_w(bf16* Wh, bf16* Wl, const uint4* imgh, const uint4* imgl, int tid) {
#pragma unroll
    for (int i = 0; i < 8; i++) {
        int c = tid + i * 256;
        int r = c >> 4, g = c & 15;
        CP_ASYNC16(sptr(Wh + r * SST + g * 8), imgh + r * 17 + g);
        CP_ASYNC16(sptr(Wl + r * SST + g * 8), imgl + r * 17 + g);
    }
}

// 3-split mma with hoisted fragments
__device__ __forceinline__ void mma_all(const bf16* Ah, const bf16* Al,
                                        const bf16* Wh, const bf16* Wl,
                                        float acc[2][4][4], int lane, int mb, int nb) {
#pragma unroll
    for (int mt = 0; mt < 2; mt++)
#pragma unroll
        for (int nt = 0; nt < 4; nt++)
#pragma unroll
            for (int q = 0; q < 4; q++) acc[mt][nt][q] = 0.f;

    int l15 = lane & 15, lq = (lane >> 4) * 8;
    int arow = mb * 32 + l15;
#pragma unroll
    for (int kc = 0; kc < 8; kc++) {
        uint32_t ah[2][4], al[2][4];
        ldsm4(ah[0], sptr(Ah + arow * SST + kc * 16 + lq));
        ldsm4(ah[1], sptr(Ah + (arow + 16) * SST + kc * 16 + lq));
        ldsm4(al[0], sptr(Al + arow * SST + kc * 16 + lq));
        ldsm4(al[1], sptr(Al + (arow + 16) * SST + kc * 16 + lq));
#pragma unroll
        for (int ntg = 0; ntg < 2; ntg++) {
            uint32_t bh[4], bl[4];
            unsigned wsoff = (kc * 16 + l15) * SST + nb * 32 + ntg * 16 + lq;
            ldsm4t(bh, sptr(Wh + wsoff));
            ldsm4t(bl, sptr(Wl + wsoff));
            float* c0 = acc[0][ntg * 2];
            float* c1 = acc[0][ntg * 2 + 1];
            float* c2 = acc[1][ntg * 2];
            float* c3 = acc[1][ntg * 2 + 1];
            mma16816(c0, ah[0], bh[0], bh[1]); mma16816(c1, ah[0], bh[2], bh[3]);
            mma16816(c2, ah[1], bh[0], bh[1]); mma16816(c3, ah[1], bh[2], bh[3]);
            mma16816(c0, al[0], bh[0], bh[1]); mma16816(c1, al[0], bh[2], bh[3]);
            mma16816(c2, al[1], bh[0], bh[1]); mma16816(c3, al[1], bh[2], bh[3]);
            mma16816(c0, ah[0], bl[0], bl[1]); mma16816(c1, ah[0], bl[2], bl[3]);
            mma16816(c2, ah[1], bl[0], bl[1]); mma16816(c3, ah[1], bl[2], bl[3]);
        }
    }
}

__device__ __forceinline__ void epi_store_xb(float acc[2][4][4], int lane, int mb, int nb, int row0) {
#pragma unroll
    for (int mt = 0; mt < 2; mt++) {
        int rl = mb * 32 + mt * 16 + (lane >> 2);
#pragma unroll
        for (int nt = 0; nt < 4; nt++) {
            int col = nb * 32 + nt * 8 + (lane & 3) * 2;
            int r0 = row0 + rl, r1 = r0 + 8;
            if (r0 < NUM_NODES)
                *reinterpret_cast<__nv_bfloat162*>(g_xb + (size_t)r0 * HID + col) =
                    __floats2bfloat162_rn(acc[mt][nt][0], acc[mt][nt][1]);
            if (r1 < NUM_NODES)
                *reinterpret_cast<__nv_bfloat162*>(g_xb + (size_t)r1 * HID + col) =
                    __floats2bfloat162_rn(acc[mt][nt][2], acc[mt][nt][3]);
        }
    }
}

// ---------------- weight image prep ----------------
__global__ void prep_w(const float* __restrict__ cf_w1,
                       const float* __restrict__ cf_w2,
                       const float* __restrict__ lin_w) {
    int m = blockIdx.x;
    const float* W = (m < 3) ? cf_w1 + (size_t)m * HID * HID
                   : (m < 6) ? cf_w2 + (size_t)(m - 3) * HID * HID
                             : lin_w + (size_t)(m - 6) * HID * HID;
    uint4* imgh = g_wimg + (size_t)m * 2 * TILE_U4;
    uint4* imgl = imgh + TILE_U4;
    int tid = threadIdx.x;
#pragma unroll
    for (int i = 0; i < 8; i++) {
        int c = tid + i * 256;
        int r = c >> 4, g = c & 15;
        const float4* src = reinterpret_cast<const float4*>(W + (size_t)r * HID + g * 8);
        float4 v0 = __ldg(src), v1 = __ldg(src + 1);
        float vv[8] = {v0.x, v0.y, v0.z, v0.w, v1.x, v1.y, v1.z, v1.w};
        unsigned ph[4], pl[4];
#pragma unroll
        for (int e = 0; e < 4; e++) {
            bf16 h0 = __float2bfloat16(vv[2 * e]);
            bf16 h1 = __float2bfloat16(vv[2 * e + 1]);
            bf16 l0 = __float2bfloat16(vv[2 * e] - __bfloat162float(h0));
            bf16 l1 = __float2bfloat16(vv[2 * e + 1] - __bfloat162float(h1));
            __nv_bfloat162 hp = __halves2bfloat162(h0, h1);
            __nv_bfloat162 lp = __halves2bfloat162(l0, l1);
            ph[e] = *reinterpret_cast<unsigned*>(&hp);
            pl[e] = *reinterpret_cast<unsigned*>(&lp);
        }
        imgh[r * 17 + g] = make_uint4(ph[0], ph[1], ph[2], ph[3]);
        imgl[r * 17 + g] = make_uint4(pl[0], pl[1], pl[2], pl[3]);
    }
}

// ---------------- persistent init + first GEMM (TM=64, 2 CTA/SM, grid 296) ----------------
__global__ void __launch_bounds__(256, 2) gemm_xb(const float* __restrict__ emb,
                                                  const int* __restrict__ z) {
    extern __shared__ char smraw[];
    SmemMMA& sm = *reinterpret_cast<SmemMMA*>(smraw);
    int tid = threadIdx.x, lane = tid & 31, wid = tid >> 5;
    int mb = wid & 1, nb = wid >> 1;

    cp_w(sm.Wh, sm.Wl, g_wimg, g_wimg + TILE_U4, tid);
    CP_COMMIT();

    int t = blockIdx.x;
    if (t < NT64) {
        int row0 = t * TM;
        int r = tid >> 2, c0 = (tid & 3) * 32;
        int gr = row0 + r;
        bool ok = gr < NUM_NODES;
        int zz = ok ? __ldg(z + gr) : 0;
        const float4* src = reinterpret_cast<const float4*>(emb + (size_t)zz * HID + c0);
        float4* hdst = reinterpret_cast<float4*>(g_h + (size_t)gr * HID + c0);
#pragma unroll
        for (int q = 0; q < 8; q++) {
            float4 v = ok ? __ldg(src + q) : f4z();
            if (ok) hdst[q] = v;
            int base = r * SST + c0 + q * 4;
            split_store(sm.Ah, sm.Al, base, v.x, v.y);
            split_store(sm.Ah, sm.Al, base + 2, v.z, v.w);
        }
    }
    CP_WAIT(0);
    __syncthreads();

    while (t < NT64) {
        int row0 = t * TM;
        float acc[2][4][4];
        mma_all(sm.Ah, sm.Al, sm.Wh, sm.Wl, acc, lane, mb, nb);
        epi_store_xb(acc, lane, mb, nb, row0);
        int tn = t + gridDim.x;
        __syncthreads();
        if (tn < NT64) {
            int row0n = tn * TM;
            int r = tid >> 2, c0 = (tid & 3) * 32;
            int gr = row0n + r;
            bool ok = gr < NUM_NODES;
            int zz = ok ? __ldg(z + gr) : 0;
            const float4* src = reinterpret_cast<const float4*>(emb + (size_t)zz * HID + c0);
            float4* hdst = reinterpret_cast<float4*>(g_h + (size_t)gr * HID + c0);
#pragma unroll
            for (int q = 0; q < 8; q++) {
                float4 v = ok ? __ldg(src + q) : f4z();
                if (ok) hdst[q] = v;
                int base = r * SST + c0 + q * 4;
                split_store(sm.Ah, sm.Al, base, v.x, v.y);
                split_store(sm.Ah, sm.Al, base + 2, v.z, v.w);
            }
            __syncthreads();
        }
        t = tn;
    }
}

// ---------------- fused node update (R13: TM=64, 2 CTA/SM, per-tile CTA) ----------------
template <int LAST>
__global__ void __launch_bounds__(256, 2) node_update(int mW2, int mWL, int mW1n,
                                                      const float* __restrict__ b2,
                                                      const float* __restrict__ bL) {
    extern __shared__ char smraw[];
    SmemMMA& sm = *reinterpret_cast<SmemMMA*>(smraw);
    int tid = threadIdx.x, lane = tid & 31, wid = tid >> 5;
    int mb = wid & 1, nb = wid >> 1;
    int row0 = blockIdx.x * TM;
    float acc[2][4][4];

    const uint4* i2 = g_wimg + (size_t)mW2 * 2 * TILE_U4;
    cp_w(sm.Wh, sm.Wl, i2, i2 + TILE_U4, tid);
    CP_COMMIT();
    load_splitA(g_agg, row0, sm.Ah, sm.Al, tid);
    CP_WAIT(0);
    __syncthreads();

    // ---- pass A: agg @ W2 ----
    mma_all(sm.Ah, sm.Al, sm.Wh, sm.Wl, acc, lane, mb, nb);
    __syncthreads();

    const uint4* iL = g_wimg + (size_t)mWL * 2 * TILE_U4;
    cp_w(sm.Wh, sm.Wl, iL, iL + TILE_U4, tid);
    CP_COMMIT();

    // epilogue A: Us = ssp(D + b2) -> Ah/Al
#pragma unroll
    for (int mt = 0; mt < 2; mt++) {
        int rl = mb * 32 + mt * 16 + (lane >> 2);
#pragma unroll
        for (int nt = 0; nt < 4; nt++) {
            int col = nb * 32 + nt * 8 + (lane & 3) * 2;
            float bb0 = __ldg(b2 + col), bb1 = __ldg(b2 + col + 1);
            split_store(sm.Ah, sm.Al, rl * SST + col,
                        sspf(acc[mt][nt][0] + bb0), sspf(acc[mt][nt][1] + bb1));
            split_store(sm.Ah, sm.Al, (rl + 8) * SST + col,
                        sspf(acc[mt][nt][2] + bb0), sspf(acc[mt][nt][3] + bb1));
        }
    }
    CP_WAIT(0);
    __syncthreads();

    // ---- pass B: Us @ WL ----
    mma_all(sm.Ah, sm.Al, sm.Wh, sm.Wl, acc, lane, mb, nb);
    __syncthreads();

    if (!LAST) {
        const uint4* iN = g_wimg + (size_t)mW1n * 2 * TILE_U4;
        cp_w(sm.Wh, sm.Wl, iN, iN + TILE_U4, tid);
        CP_COMMIT();
    }

    // epilogue B: h += D + bL ; stage h_new into Ah/Al
#pragma unroll
    for (int mt = 0; mt < 2; mt++) {
        int rl = mb * 32 + mt * 16 + (lane >> 2);
#pragma unroll
        for (int nt = 0; nt < 4; nt++) {
            int col = nb * 32 + nt * 8 + (lane & 3) * 2;
            float bb0 = __ldg(bL + col), bb1 = __ldg(bL + col + 1);
#pragma unroll
            for (int half = 0; half < 2; half++) {
                int r = row0 + rl + half * 8;
                bool ok = r < NUM_NODES;
                float2 hv = ok ? *reinterpret_cast<const float2*>(g_h + (size_t)r * HID + col)
                               : make_float2(0.f, 0.f);
                float v0 = hv.x + acc[mt][nt][half * 2] + bb0;
                float v1 = hv.y + acc[mt][nt][half * 2 + 1] + bb1;
                if (ok)
                    *reinterpret_cast<float2*>(g_h + (size_t)r * HID + col) = make_float2(v0, v1);
                if (!LAST)
                    split_store(sm.Ah, sm.Al, (rl + half * 8) * SST + col, v0, v1);
            }
        }
    }
    if (LAST) return;

    CP_WAIT(0);
    __syncthreads();

    // ---- pass C: xb = h_new @ W1n ----
    mma_all(sm.Ah, sm.Al, sm.Wh, sm.Wl, acc, lane, mb, nb);
    epi_store_xb(acc, lane, mb, nb, row0);
}

// ---------------- setup kernels ----------------
__global__ void zero_meta() {
    int i = blockIdx.x * blockDim.x + threadIdx.x;
    if (i < SCAN_N) g_deg[i] = 0;
}

__global__ void prep_pos4(const float* __restrict__ pos) {
    int n = blockIdx.x * blockDim.x + threadIdx.x;
    if (n >= NUM_NODES) return;
    g_pos4[n] = make_float4(__ldg(pos + n * 3), __ldg(pos + n * 3 + 1),
                            __ldg(pos + n * 3 + 2), 0.f);
}

__global__ void prep_edges(const float* __restrict__ shift,
                           const int* __restrict__ ei) {
    int e = blockIdx.x * blockDim.x + threadIdx.x;
    if (e >= NUM_EDGES) return;
    int s = __ldg(ei + e);
    int d = __ldg(ei + NUM_EDGES + e);
    float4 ps = __ldg(&g_pos4[s]);
    float4 pd = __ldg(&g_pos4[d]);
    float sx = __ldg(shift + e * 3 + 0);
    float sy = __ldg(shift + e * 3 + 1);
    float sz = __ldg(shift + e * 3 + 2);
    float dx = ps.x - pd.x - sx;
    float dy = ps.y - pd.y - sy;
    float dz = ps.z - pd.z - sz;
    float w = sqrtf(dx * dx + dy * dy + dz * dz);
    float t = -1.0f;
    if (w < WCUT) {
        t = w * ((float)(TBL - 1) / WTOP);
        atomicAdd(&g_deg[d + 1], 1);
    }
    g_epack[e] = make_int4(s, d, __float_as_int(t), 0);
}

__device__ __forceinline__ int blk_incl_scan(int v, int tid, int* warp_sums) {
    int x = v;
#pragma unroll
    for (int o = 1; o < 32; o <<= 1) {
        int y = __shfl_up_sync(0xffffffffu, x, o);
        if ((tid & 31) >= o) x += y;
    }
    if ((tid & 31) == 31) warp_sums[tid >> 5] = x;
    __syncthreads();
    if (tid < 32) {
        int s = warp_sums[tid];
#pragma unroll
        for (int o = 1; o < 32; o <<= 1) {
            int y = __shfl_up_sync(0xffffffffu, s, o);
            if (tid >= o) s += y;
        }
        warp_sums[tid] = s;
    }
    __syncthreads();
    return x + ((tid >= 32) ? warp_sums[(tid >> 5) - 1] : 0);
}

__global__ void scan_block() {
    __shared__ int ws[32];
    int tid = threadIdx.x;
    int gid = blockIdx.x * 1024 + tid;
    int v = (gid < SCAN_N) ? g_deg[gid] : 0;
    int incl = blk_incl_scan(v, tid, ws);
    if (gid < SCAN_N) g_off[gid] = incl;
    if (tid == 1023) g_part[blockIdx.x] = incl;
}

__global__ void scan_part() {
    __shared__ int ws[32];
    int tid = threadIdx.x;
    int v = (tid < 49) ? g_part[tid] : 0;
    int incl = blk_incl_scan(v, tid, ws);
    if (tid < 64) g_part[tid] = incl - v;
    if (tid < NUM_GRAPHS) { g_sums[tid] = 0.f; g_cnts[tid] = 0.f; }
}

__global__ void scan_add() {
    int tid = threadIdx.x;
    int gid = blockIdx.x * 1024 + tid;
    if (gid >= SCAN_N) return;
    int val = g_off[gid] + g_part[blockIdx.x];
    g_off[gid] = val;
    if (gid < NUM_NODES) g_cur[gid] = val;
}

__global__ void scatter_csr() {
    int e = blockIdx.x * blockDim.x + threadIdx.x;
    if (e >= NUM_EDGES) return;
    int4 pk = __ldg(&g_epack[e]);
    if (__int_as_float(pk.z) < 0.f) return;
    int pos = atomicAdd(&g_cur[pk.y], 1);
    g_esrc[pos] = make_int2(pk.x, pk.z);
}

// ---------------- Wf(w) table ----------------
__global__ void build_val(const float* __restrict__ w1, const float* __restrict__ b1,
                          const float* __restrict__ w2, const float* __restrict__ b2) {
    int j = blockIdx.x, it = blockIdx.y, tid = threadIdx.x;
    __shared__ float attr[NUM_G];
    __shared__ float act[HID];
    float w = (float)j * (WTOP / (float)(TBL - 1));
    if (tid < NUM_G) {
        float off = (float)tid * (8.0f / 49.0f);
        float dlt = w - off;
        attr[tid] = __expf(GCOEFF * dlt * dlt);
    }
    __syncthreads();
    const float* W1 = w1 + it * NUM_G * HID;
    float u = b1[it * HID + tid];
#pragma unroll
    for (int g = 0; g < NUM_G; g++) u += attr[g] * W1[g * HID + tid];
    act[tid] = sspf(u);
    __syncthreads();
    const float* W2 = w2 + it * HID * HID;
    float v = b2[it * HID + tid];
#pragma unroll 8
    for (int k = 0; k < HID; k++) v += act[k] * W2[k * HID + tid];
    float C = 0.5f * (cosf(w * PI_OVER_8) + 1.0f);
    g_tval[(size_t)(it * TBL + j) * HID + tid] = v * C;
}

__global__ void build_pack() {
    int j = blockIdx.x, it = blockIdx.y, t = threadIdx.x;
    size_t row = (size_t)(it * TBL + j) * HID;
    float v0 = g_tval[row + 2 * t];
    float v1 = g_tval[row + 2 * t + 1];
    float n0 = v0, n1 = v1;
    if (j < TBL - 1) {
        n0 = g_tval[row + HID + 2 * t];
        n1 = g_tval[row + HID + 2 * t + 1];
    }
    __nv_bfloat162 vv = __floats2bfloat162_rn(v0, v1);
    __nv_bfloat162 ss = __floats2bfloat162_rn(n0 - v0, n1 - v1);
    uint2 pk = make_uint2(*reinterpret_cast<unsigned*>(&vv),
                          *reinterpret_cast<unsigned*>(&ss));
    reinterpret_cast<uint2*>(g_tblb)[((size_t)(it * TBL + j) * 64) + t] = pk;
}

// ---------------- gather: warp per node ----------------
__global__ void gather(const uint4* __restrict__ tbl) {
    int n = (blockIdx.x * blockDim.x + threadIdx.x) >> 5;
    if (n >= NUM_NODES) return;
    int lane = threadIdx.x & 31;
    int beg = __ldg(&g_off[n]);
    int end = __ldg(&g_off[n + 1]);
    float4 acc = f4z();
#pragma unroll 4
    for (int e = beg; e < end; e++) {
        int2 p = __ldg(&g_esrc[e]);
        float t = __int_as_float(p.y);
        int bin = (int)t;
        float f = t - (float)bin;
        uint4 tv = __ldg(tbl + (size_t)bin * 32 + lane);
        float2 v01 = __bfloat1622float2(*reinterpret_cast<__nv_bfloat162*>(&tv.x));
        float2 s01 = __bfloat1622float2(*reinterpret_cast<__nv_bfloat162*>(&tv.y));
        float2 v23 = __bfloat1622float2(*reinterpret_cast<__nv_bfloat162*>(&tv.z));
        float2 s23 = __bfloat1622float2(*reinterpret_cast<__nv_bfloat162*>(&tv.w));
        uint2 xb = __ldg(reinterpret_cast<const uint2*>(g_xb + (size_t)p.x * HID) + lane);
        float2 x01 = __bfloat1622float2(*reinterpret_cast<__nv_bfloat162*>(&xb.x));
        float2 x23 = __bfloat1622float2(*reinterpret_cast<__nv_bfloat162*>(&xb.y));
        acc.x = fmaf(x01.x, fmaf(f, s01.x, v01.x), acc.x);
        acc.y = fmaf(x01.y, fmaf(f, s01.y, v01.y), acc.y);
        acc.z = fmaf(x23.x, fmaf(f, s23.x, v23.x), acc.z);
        acc.w = fmaf(x23.y, fmaf(f, s23.y, v23.y), acc.w);
    }
    *reinterpret_cast<float4*>(g_agg + (size_t)n * HID + lane * 4) = acc;
}

// ---------------- readout ----------------
__global__ void head_kernel(const float* __restrict__ hw1, const float* __restrict__ hb1,
                            const float* __restrict__ hw2, const float* __restrict__ hb2,
                            const int* __restrict__ batch) {
    int n = (blockIdx.x * blockDim.x + threadIdx.x) >> 5;
    if (n >= NUM_NODES) return;
    int lane = threadIdx.x & 31;
    const float* hrow = g_h + (size_t)n * HID;
    float hr[4];
#pragma unroll
    for (int q = 0; q < 4; q++) hr[q] = hrow[q * 32 + lane];
    float u0 = hb1[lane];
    float u1 = hb1[lane + 32];
#pragma unroll
    for (int k = 0; k < HID; k++) {
        float hv = __shfl_sync(0xffffffffu, hr[k >> 5], k & 31);
        u0 = fmaf(hv, hw1[k * 64 + lane], u0);
        u1 = fmaf(hv, hw1[k * 64 + lane + 32], u1);
    }
    float part = sspf(u0) * hw2[lane] + sspf(u1) * hw2[lane + 32];
#pragma unroll
    for (int o = 16; o; o >>= 1) part += __shfl_down_sync(0xffffffffu, part, o);
    if (lane == 0) {
        int b = batch[n];
        atomicAdd(&g_sums[b], part + hb2[0]);
        atomicAdd(&g_cnts[b], 1.0f);
    }
}

__global__ void finalize(float* __restrict__ out) {
    int g = threadIdx.x;
    if (g < NUM_GRAPHS) out[g] = g_sums[g] / fmaxf(g_cnts[g], 1.0f);
}

// ---------------- launcher ----------------
extern "C" void kernel_launch(void* const* d_in, const int* in_sizes, int n_in,
                              void* d_out, int out_size) {
    const float* pos    = (const float*)d_in[0];
    const float* shift  = (const float*)d_in[1];
    const float* emb    = (const float*)d_in[2];
    const float* mlp_w1 = (const float*)d_in[3];
    const float* mlp_b1 = (const float*)d_in[4];
    const float* mlp_w2 = (const float*)d_in[5];
    const float* mlp_b2 = (const float*)d_in[6];
    const float* cf_w1  = (const float*)d_in[7];
    const float* cf_w2  = (const float*)d_in[8];
    const float* cf_b2  = (const float*)d_in[9];
    const float* lin_w  = (const float*)d_in[10];
    const float* lin_b  = (const float*)d_in[11];
    const float* hw1    = (const float*)d_in[12];
    const float* hb1    = (const float*)d_in[13];
    const float* hw2    = (const float*)d_in[14];
    const float* hb2    = (const float*)d_in[15];
    const int*   z      = (const int*)d_in[16];
    const int*   ei     = (const int*)d_in[17];
    const int*   batch  = (const int*)d_in[18];
    float* out = (float*)d_out;

    uint4* tblb_p;
    cudaGetSymbolAddress((void**)&tblb_p, g_tblb);

    cudaFuncSetAttribute(gemm_xb,        cudaFuncAttributeMaxDynamicSharedMemorySize, SMEM_MMA);
    cudaFuncSetAttribute(node_update<0>, cudaFuncAttributeMaxDynamicSharedMemorySize, SMEM_MMA);
    cudaFuncSetAttribute(node_update<1>, cudaFuncAttributeMaxDynamicSharedMemorySize, SMEM_MMA);

    int gblk = (NUM_NODES + TM - 1) / TM;   // 782
    int sgrid = (SCAN_N + 1023) / 1024;
    dim3 tgrid(TBL, NUM_INTER);

    zero_meta<<<sgrid, 1024>>>();
    prep_w<<<9, 256>>>(cf_w1, cf_w2, lin_w);
    prep_pos4<<<(NUM_NODES + 255) / 256, 256>>>(pos);
    gemm_xb<<<296, 256, SMEM_MMA>>>(emb, z);                        // profiled slot
    build_val<<<tgrid, 128>>>(mlp_w1, mlp_b1, mlp_w2, mlp_b2);
    build_pack<<<tgrid, 64>>>();
    prep_edges<<<(NUM_EDGES + 255) / 256, 256>>>(shift, ei);
    scan_block<<<sgrid, 1024>>>();
    scan_part<<<1, 1024>>>();
    scan_add<<<sgrid, 1024>>>();
    scatter_csr<<<(NUM_EDGES + 255) / 256, 256>>>();

    int wgrid = (int)(((long long)NUM_NODES * 32 + 255) / 256);
    for (int i = 0; i < NUM_INTER; i++) {
        gather<<<wgrid, 256>>>(tblb_p + (size_t)i * TBL * 32);
        const float* b2p = cf_b2 + (size_t)i * HID;
        const float* bLp = lin_b + (size_t)i * HID;
        if (i < NUM_INTER - 1) {
            node_update<0><<<gblk, 256, SMEM_MMA>>>(3 + i, 6 + i, i + 1, b2p, bLp);
        } else {
            node_update<1><<<gblk, 256, SMEM_MMA>>>(3 + i, 6 + i, 0, b2p, bLp);
        }
    }

    head_kernel<<<wgrid, 256>>>(hw1, hb1, hw2, hb2, batch);
    finalize<<<1, 128>>>(out);
}

// round 16
// speedup vs baseline: 1.0862x; 1.0162x over previous
#include <cuda_runtime.h>
#include <cuda_bf16.h>
#include <math.h>
#include <stdint.h>

#define NUM_NODES 50000
#define NUM_EDGES 1600000
#define NUM_GRAPHS 128
#define HID 128
#define NUM_G 50
#define NUM_INTER 3
#define TBL 1024
#define WTOP 10.0f
#define WCUT 9.6f
#define LOG2F_ 0.6931471805599453f
#define PI_OVER_8 0.39269908169872414f
#define GCOEFF (-18.7578125f)
#define SCAN_N (NUM_NODES + 1)
#define SST 136
#define TM 64
#define TILE_U4 (128 * 17)
#define NT64 ((NUM_NODES + 63) / 64)

typedef unsigned long long u64;
typedef __nv_bfloat16 bf16;

// ---------------- static scratch ----------------
__device__ float  g_tval[NUM_INTER * TBL * HID];
__device__ uint4  g_tblb[NUM_INTER * TBL * 32];
__device__ uint4  g_wimg[9 * 2 * TILE_U4];
__device__ float4 g_pos4[NUM_NODES];
__device__ float  g_h[NUM_NODES * HID];
__device__ bf16   g_xb[NUM_NODES * HID];
__device__ float  g_agg[NUM_NODES * HID];
__device__ int4   g_epack[NUM_EDGES];
__device__ int2   g_esrc[NUM_EDGES];
__device__ int    g_deg[SCAN_N];
__device__ int    g_off[SCAN_N];
__device__ int    g_cur[NUM_NODES];
__device__ int    g_part[64];
__device__ float  g_sums[NUM_GRAPHS];
__device__ float  g_cnts[NUM_GRAPHS];

__device__ __forceinline__ float sspf(float v) {
    float sp = (v > 20.0f) ? v : log1pf(__expf(v));
    return sp - LOG2F_;
}
__device__ __forceinline__ float4 f4z() { return make_float4(0.f, 0.f, 0.f, 0.f); }

// ---------------- cp.async ----------------
#define CP_ASYNC16(saddr, gptr) \
    asm volatile("cp.async.ca.shared.global [%0], [%1], 16;" :: "r"(saddr), "l"(gptr) : "memory")
#define CP_COMMIT() asm volatile("cp.async.commit_group;" ::: "memory")
#define CP_WAIT(n)  asm volatile("cp.async.wait_group %0;" :: "n"(n) : "memory")

// ---------------- MMA smem ----------------
struct SmemMMA {
    bf16 Ah[TM * SST];
    bf16 Al[TM * SST];
    bf16 Wh[128 * SST];
    bf16 Wl[128 * SST];
};
#define SMEM_MMA ((int)sizeof(SmemMMA))

__device__ __forceinline__ unsigned sptr(const void* p) {
    return (unsigned)__cvta_generic_to_shared(p);
}
__device__ __forceinline__ void ldsm4(uint32_t* r, unsigned addr) {
    asm volatile("ldmatrix.sync.aligned.m8n8.x4.shared.b16 {%0,%1,%2,%3}, [%4];"
                 : "=r"(r[0]), "=r"(r[1]), "=r"(r[2]), "=r"(r[3]) : "r"(addr));
}
__device__ __forceinline__ void ldsm4t(uint32_t* r, unsigned addr) {
    asm volatile("ldmatrix.sync.aligned.m8n8.x4.trans.shared.b16 {%0,%1,%2,%3}, [%4];"
                 : "=r"(r[0]), "=r"(r[1]), "=r"(r[2]), "=r"(r[3]) : "r"(addr));
}
__device__ __forceinline__ void mma16816(float* c, const uint32_t* a, uint32_t b0, uint32_t b1) {
    asm volatile("mma.sync.aligned.m16n8k16.row.col.f32.bf16.bf16.f32 "
                 "{%0,%1,%2,%3}, {%4,%5,%6,%7}, {%8,%9}, {%0,%1,%2,%3};"
                 : "+f"(c[0]), "+f"(c[1]), "+f"(c[2]), "+f"(c[3])
                 : "r"(a[0]), "r"(a[1]), "r"(a[2]), "r"(a[3]), "r"(b0), "r"(b1));
}

__device__ __forceinline__ void split_store(bf16* Ah, bf16* Al, int idx, float v0, float v1) {
    bf16 h0 = __float2bfloat16(v0), h1 = __float2bfloat16(v1);
    bf16 l0 = __float2bfloat16(v0 - __bfloat162float(h0));
    bf16 l1 = __float2bfloat16(v1 - __bfloat162float(h1));
    *reinterpret_cast<__nv_bfloat162*>(Ah + idx) = __halves2bfloat162(h0, h1);
    *reinterpret_cast<__nv_bfloat162*>(Al + idx) = __halves2bfloat162(l0, l1);
}

__device__ __forceinline__ void load_splitA(const float* __restrict__ Ag, int row0,
                                            bf16* Ah, bf16* Al, int tid) {
    int r = tid >> 2, c0 = (tid & 3) * 32;
    bool ok = (row0 + r) < NUM_NODES;
    const float4* src = reinterpret_cast<const float4*>(Ag + (size_t)(row0 + r) * HID + c0);
#pragma unroll
    for (int q = 0; q < 8; q++) {
        float4 v = ok ? __ldg(src + q) : f4z();
        int base = r * SST + c0 + q * 4;
        split_store(Ah, Al, base, v.x, v.y);
        split_store(Ah, Al, base + 2, v.z, v.w);
    }
}

__device__ __forceinline__ void cp_w(bf16* Wh, bf16* Wl, const uint4* imgh, const uint4* imgl, int tid) {
#pragma unroll
    for (int i = 0; i < 8; i++) {
        int c = tid + i * 256;
        int r = c >> 4, g = c & 15;
        CP_ASYNC16(sptr(Wh + r * SST + g * 8), imgh + r * 17 + g);
        CP_ASYNC16(sptr(Wl + r * SST + g * 8), imgl + r * 17 + g);
    }
}

// 3-split mma with hoisted fragments
__device__ __forceinline__ void mma_all(const bf16* Ah, const bf16* Al,
                                        const bf16* Wh, const bf16* Wl,
                                        float acc[2][4][4], int lane, int mb, int nb) {
#pragma unroll
    for (int mt = 0; mt < 2; mt++)
#pragma unroll
        for (int nt = 0; nt < 4; nt++)
#pragma unroll
            for (int q = 0; q < 4; q++) acc[mt][nt][q] = 0.f;

    int l15 = lane & 15, lq = (lane >> 4) * 8;
    int arow = mb * 32 + l15;
#pragma unroll
    for (int kc = 0; kc < 8; kc++) {
        uint32_t ah[2][4], al[2][4];
        ldsm4(ah[0], sptr(Ah + arow * SST + kc * 16 + lq));
        ldsm4(ah[1], sptr(Ah + (arow + 16) * SST + kc * 16 + lq));
        ldsm4(al[0], sptr(Al + arow * SST + kc * 16 + lq));
        ldsm4(al[1], sptr(Al + (arow + 16) * SST + kc * 16 + lq));
#pragma unroll
        for (int ntg = 0; ntg < 2; ntg++) {
            uint32_t bh[4], bl[4];
            unsigned wsoff = (kc * 16 + l15) * SST + nb * 32 + ntg * 16 + lq;
            ldsm4t(bh, sptr(Wh + wsoff));
            ldsm4t(bl, sptr(Wl + wsoff));
            float* c0 = acc[0][ntg * 2];
            float* c1 = acc[0][ntg * 2 + 1];
            float* c2 = acc[1][ntg * 2];
            float* c3 = acc[1][ntg * 2 + 1];
            mma16816(c0, ah[0], bh[0], bh[1]); mma16816(c1, ah[0], bh[2], bh[3]);
            mma16816(c2, ah[1], bh[0], bh[1]); mma16816(c3, ah[1], bh[2], bh[3]);
            mma16816(c0, al[0], bh[0], bh[1]); mma16816(c1, al[0], bh[2], bh[3]);
            mma16816(c2, al[1], bh[0], bh[1]); mma16816(c3, al[1], bh[2], bh[3]);
            mma16816(c0, ah[0], bl[0], bl[1]); mma16816(c1, ah[0], bl[2], bl[3]);
            mma16816(c2, ah[1], bl[0], bl[1]); mma16816(c3, ah[1], bl[2], bl[3]);
        }
    }
}

__device__ __forceinline__ void epi_store_xb(float acc[2][4][4], int lane, int mb, int nb, int row0) {
#pragma unroll
    for (int mt = 0; mt < 2; mt++) {
        int rl = mb * 32 + mt * 16 + (lane >> 2);
#pragma unroll
        for (int nt = 0; nt < 4; nt++) {
            int col = nb * 32 + nt * 8 + (lane & 3) * 2;
            int r0 = row0 + rl, r1 = r0 + 8;
            if (r0 < NUM_NODES)
                *reinterpret_cast<__nv_bfloat162*>(g_xb + (size_t)r0 * HID + col) =
                    __floats2bfloat162_rn(acc[mt][nt][0], acc[mt][nt][1]);
            if (r1 < NUM_NODES)
                *reinterpret_cast<__nv_bfloat162*>(g_xb + (size_t)r1 * HID + col) =
                    __floats2bfloat162_rn(acc[mt][nt][2], acc[mt][nt][3]);
        }
    }
}

// ---------------- weight image prep ----------------
__global__ void prep_w(const float* __restrict__ cf_w1,
                       const float* __restrict__ cf_w2,
                       const float* __restrict__ lin_w) {
    int m = blockIdx.x;
    const float* W = (m < 3) ? cf_w1 + (size_t)m * HID * HID
                   : (m < 6) ? cf_w2 + (size_t)(m - 3) * HID * HID
                             : lin_w + (size_t)(m - 6) * HID * HID;
    uint4* imgh = g_wimg + (size_t)m * 2 * TILE_U4;
    uint4* imgl = imgh + TILE_U4;
    int tid = threadIdx.x;
#pragma unroll
    for (int i = 0; i < 8; i++) {
        int c = tid + i * 256;
        int r = c >> 4, g = c & 15;
        const float4* src = reinterpret_cast<const float4*>(W + (size_t)r * HID + g * 8);
        float4 v0 = __ldg(src), v1 = __ldg(src + 1);
        float vv[8] = {v0.x, v0.y, v0.z, v0.w, v1.x, v1.y, v1.z, v1.w};
        unsigned ph[4], pl[4];
#pragma unroll
        for (int e = 0; e < 4; e++) {
            bf16 h0 = __float2bfloat16(vv[2 * e]);
            bf16 h1 = __float2bfloat16(vv[2 * e + 1]);
            bf16 l0 = __float2bfloat16(vv[2 * e] - __bfloat162float(h0));
            bf16 l1 = __float2bfloat16(vv[2 * e + 1] - __bfloat162float(h1));
            __nv_bfloat162 hp = __halves2bfloat162(h0, h1);
            __nv_bfloat162 lp = __halves2bfloat162(l0, l1);
            ph[e] = *reinterpret_cast<unsigned*>(&hp);
            pl[e] = *reinterpret_cast<unsigned*>(&lp);
        }
        imgh[r * 17 + g] = make_uint4(ph[0], ph[1], ph[2], ph[3]);
        imgl[r * 17 + g] = make_uint4(pl[0], pl[1], pl[2], pl[3]);
    }
}

// ---------------- persistent init + first GEMM (TM=64, 2 CTA/SM, grid 296) ----------------
__global__ void __launch_bounds__(256, 2) gemm_xb(const float* __restrict__ emb,
                                                  const int* __restrict__ z) {
    extern __shared__ char smraw[];
    SmemMMA& sm = *reinterpret_cast<SmemMMA*>(smraw);
    int tid = threadIdx.x, lane = tid & 31, wid = tid >> 5;
    int mb = wid & 1, nb = wid >> 1;

    cp_w(sm.Wh, sm.Wl, g_wimg, g_wimg + TILE_U4, tid);
    CP_COMMIT();

    int t = blockIdx.x;
    if (t < NT64) {
        int row0 = t * TM;
        int r = tid >> 2, c0 = (tid & 3) * 32;
        int gr = row0 + r;
        bool ok = gr < NUM_NODES;
        int zz = ok ? __ldg(z + gr) : 0;
        const float4* src = reinterpret_cast<const float4*>(emb + (size_t)zz * HID + c0);
        float4* hdst = reinterpret_cast<float4*>(g_h + (size_t)gr * HID + c0);
#pragma unroll
        for (int q = 0; q < 8; q++) {
            float4 v = ok ? __ldg(src + q) : f4z();
            if (ok) hdst[q] = v;
            int base = r * SST + c0 + q * 4;
            split_store(sm.Ah, sm.Al, base, v.x, v.y);
            split_store(sm.Ah, sm.Al, base + 2, v.z, v.w);
        }
    }
    CP_WAIT(0);
    __syncthreads();

    while (t < NT64) {
        int row0 = t * TM;
        float acc[2][4][4];
        mma_all(sm.Ah, sm.Al, sm.Wh, sm.Wl, acc, lane, mb, nb);
        epi_store_xb(acc, lane, mb, nb, row0);
        int tn = t + gridDim.x;
        __syncthreads();
        if (tn < NT64) {
            int row0n = tn * TM;
            int r = tid >> 2, c0 = (tid & 3) * 32;
            int gr = row0n + r;
            bool ok = gr < NUM_NODES;
            int zz = ok ? __ldg(z + gr) : 0;
            const float4* src = reinterpret_cast<const float4*>(emb + (size_t)zz * HID + c0);
            float4* hdst = reinterpret_cast<float4*>(g_h + (size_t)gr * HID + c0);
#pragma unroll
            for (int q = 0; q < 8; q++) {
                float4 v = ok ? __ldg(src + q) : f4z();
                if (ok) hdst[q] = v;
                int base = r * SST + c0 + q * 4;
                split_store(sm.Ah, sm.Al, base, v.x, v.y);
                split_store(sm.Ah, sm.Al, base + 2, v.z, v.w);
            }
            __syncthreads();
        }
        t = tn;
    }
}

// ---------------- fused node update (TM=64, 2 CTA/SM, per-tile CTA) ----------------
template <int LAST>
__global__ void __launch_bounds__(256, 2) node_update(int mW2, int mWL, int mW1n,
                                                      const float* __restrict__ b2,
                                                      const float* __restrict__ bL) {
    extern __shared__ char smraw[];
    SmemMMA& sm = *reinterpret_cast<SmemMMA*>(smraw);
    int tid = threadIdx.x, lane = tid & 31, wid = tid >> 5;
    int mb = wid & 1, nb = wid >> 1;
    int row0 = blockIdx.x * TM;
    float acc[2][4][4];

    const uint4* i2 = g_wimg + (size_t)mW2 * 2 * TILE_U4;
    cp_w(sm.Wh, sm.Wl, i2, i2 + TILE_U4, tid);
    CP_COMMIT();
    load_splitA(g_agg, row0, sm.Ah, sm.Al, tid);
    CP_WAIT(0);
    __syncthreads();

    // ---- pass A: agg @ W2 ----
    mma_all(sm.Ah, sm.Al, sm.Wh, sm.Wl, acc, lane, mb, nb);
    __syncthreads();

    const uint4* iL = g_wimg + (size_t)mWL * 2 * TILE_U4;
    cp_w(sm.Wh, sm.Wl, iL, iL + TILE_U4, tid);
    CP_COMMIT();

    // epilogue A: Us = ssp(D + b2) -> Ah/Al
#pragma unroll
    for (int mt = 0; mt < 2; mt++) {
        int rl = mb * 32 + mt * 16 + (lane >> 2);
#pragma unroll
        for (int nt = 0; nt < 4; nt++) {
            int col = nb * 32 + nt * 8 + (lane & 3) * 2;
            float bb0 = __ldg(b2 + col), bb1 = __ldg(b2 + col + 1);
            split_store(sm.Ah, sm.Al, rl * SST + col,
                        sspf(acc[mt][nt][0] + bb0), sspf(acc[mt][nt][1] + bb1));
            split_store(sm.Ah, sm.Al, (rl + 8) * SST + col,
                        sspf(acc[mt][nt][2] + bb0), sspf(acc[mt][nt][3] + bb1));
        }
    }
    CP_WAIT(0);
    __syncthreads();

    // ---- pass B: Us @ WL ----
    mma_all(sm.Ah, sm.Al, sm.Wh, sm.Wl, acc, lane, mb, nb);
    __syncthreads();

    if (!LAST) {
        const uint4* iN = g_wimg + (size_t)mW1n * 2 * TILE_U4;
        cp_w(sm.Wh, sm.Wl, iN, iN + TILE_U4, tid);
        CP_COMMIT();
    }

    // epilogue B: h += D + bL ; stage h_new into Ah/Al
#pragma unroll
    for (int mt = 0; mt < 2; mt++) {
        int rl = mb * 32 + mt * 16 + (lane >> 2);
#pragma unroll
        for (int nt = 0; nt < 4; nt++) {
            int col = nb * 32 + nt * 8 + (lane & 3) * 2;
            float bb0 = __ldg(bL + col), bb1 = __ldg(bL + col + 1);
#pragma unroll
            for (int half = 0; half < 2; half++) {
                int r = row0 + rl + half * 8;
                bool ok = r < NUM_NODES;
                float2 hv = ok ? *reinterpret_cast<const float2*>(g_h + (size_t)r * HID + col)
                               : make_float2(0.f, 0.f);
                float v0 = hv.x + acc[mt][nt][half * 2] + bb0;
                float v1 = hv.y + acc[mt][nt][half * 2 + 1] + bb1;
                if (ok)
                    *reinterpret_cast<float2*>(g_h + (size_t)r * HID + col) = make_float2(v0, v1);
                if (!LAST)
                    split_store(sm.Ah, sm.Al, (rl + half * 8) * SST + col, v0, v1);
            }
        }
    }
    if (LAST) return;

    CP_WAIT(0);
    __syncthreads();

    // ---- pass C: xb = h_new @ W1n ----
    mma_all(sm.Ah, sm.Al, sm.Wh, sm.Wl, acc, lane, mb, nb);
    epi_store_xb(acc, lane, mb, nb, row0);
}

// ---------------- setup kernels ----------------
__global__ void zero_meta() {
    int i = blockIdx.x * blockDim.x + threadIdx.x;
    if (i < SCAN_N) g_deg[i] = 0;
}

__global__ void prep_pos4(const float* __restrict__ pos) {
    int n = blockIdx.x * blockDim.x + threadIdx.x;
    if (n >= NUM_NODES) return;
    g_pos4[n] = make_float4(__ldg(pos + n * 3), __ldg(pos + n * 3 + 1),
                            __ldg(pos + n * 3 + 2), 0.f);
}

__global__ void prep_edges(const float* __restrict__ shift,
                           const int* __restrict__ ei) {
    int e = blockIdx.x * blockDim.x + threadIdx.x;
    if (e >= NUM_EDGES) return;
    int s = __ldg(ei + e);
    int d = __ldg(ei + NUM_EDGES + e);
    float4 ps = __ldg(&g_pos4[s]);
    float4 pd = __ldg(&g_pos4[d]);
    float sx = __ldg(shift + e * 3 + 0);
    float sy = __ldg(shift + e * 3 + 1);
    float sz = __ldg(shift + e * 3 + 2);
    float dx = ps.x - pd.x - sx;
    float dy = ps.y - pd.y - sy;
    float dz = ps.z - pd.z - sz;
    float w = sqrtf(dx * dx + dy * dy + dz * dz);
    float t = -1.0f;
    if (w < WCUT) {
        t = w * ((float)(TBL - 1) / WTOP);
        atomicAdd(&g_deg[d + 1], 1);
    }
    g_epack[e] = make_int4(s, d, __float_as_int(t), 0);
}

__device__ __forceinline__ int blk_incl_scan(int v, int tid, int* warp_sums) {
    int x = v;
#pragma unroll
    for (int o = 1; o < 32; o <<= 1) {
        int y = __shfl_up_sync(0xffffffffu, x, o);
        if ((tid & 31) >= o) x += y;
    }
    if ((tid & 31) == 31) warp_sums[tid >> 5] = x;
    __syncthreads();
    if (tid < 32) {
        int s = warp_sums[tid];
#pragma unroll
        for (int o = 1; o < 32; o <<= 1) {
            int y = __shfl_up_sync(0xffffffffu, s, o);
            if (tid >= o) s += y;
        }
        warp_sums[tid] = s;
    }
    __syncthreads();
    return x + ((tid >= 32) ? warp_sums[(tid >> 5) - 1] : 0);
}

__global__ void scan_block() {
    __shared__ int ws[32];
    int tid = threadIdx.x;
    int gid = blockIdx.x * 1024 + tid;
    int v = (gid < SCAN_N) ? g_deg[gid] : 0;
    int incl = blk_incl_scan(v, tid, ws);
    if (gid < SCAN_N) g_off[gid] = incl;
    if (tid == 1023) g_part[blockIdx.x] = incl;
}

__global__ void scan_part() {
    __shared__ int ws[32];
    int tid = threadIdx.x;
    int v = (tid < 49) ? g_part[tid] : 0;
    int incl = blk_incl_scan(v, tid, ws);
    if (tid < 64) g_part[tid] = incl - v;
    if (tid < NUM_GRAPHS) { g_sums[tid] = 0.f; g_cnts[tid] = 0.f; }
}

__global__ void scan_add() {
    int tid = threadIdx.x;
    int gid = blockIdx.x * 1024 + tid;
    if (gid >= SCAN_N) return;
    int val = g_off[gid] + g_part[blockIdx.x];
    g_off[gid] = val;
    if (gid < NUM_NODES) g_cur[gid] = val;
}

__global__ void scatter_csr() {
    int e = blockIdx.x * blockDim.x + threadIdx.x;
    if (e >= NUM_EDGES) return;
    int4 pk = __ldg(&g_epack[e]);
    if (__int_as_float(pk.z) < 0.f) return;
    int pos = atomicAdd(&g_cur[pk.y], 1);
    g_esrc[pos] = make_int2(pk.x, pk.z);
}

// ---------------- Wf(w) table ----------------
__global__ void build_val(const float* __restrict__ w1, const float* __restrict__ b1,
                          const float* __restrict__ w2, const float* __restrict__ b2) {
    int j = blockIdx.x, it = blockIdx.y, tid = threadIdx.x;
    __shared__ float attr[NUM_G];
    __shared__ float act[HID];
    float w = (float)j * (WTOP / (float)(TBL - 1));
    if (tid < NUM_G) {
        float off = (float)tid * (8.0f / 49.0f);
        float dlt = w - off;
        attr[tid] = __expf(GCOEFF * dlt * dlt);
    }
    __syncthreads();
    const float* W1 = w1 + it * NUM_G * HID;
    float u = b1[it * HID + tid];
#pragma unroll
    for (int g = 0; g < NUM_G; g++) u += attr[g] * W1[g * HID + tid];
    act[tid] = sspf(u);
    __syncthreads();
    const float* W2 = w2 + it * HID * HID;
    float v = b2[it * HID + tid];
#pragma unroll 8
    for (int k = 0; k < HID; k++) v += act[k] * W2[k * HID + tid];
    float C = 0.5f * (cosf(w * PI_OVER_8) + 1.0f);
    g_tval[(size_t)(it * TBL + j) * HID + tid] = v * C;
}

__global__ void build_pack() {
    int j = blockIdx.x, it = blockIdx.y, t = threadIdx.x;
    size_t row = (size_t)(it * TBL + j) * HID;
    float v0 = g_tval[row + 2 * t];
    float v1 = g_tval[row + 2 * t + 1];
    float n0 = v0, n1 = v1;
    if (j < TBL - 1) {
        n0 = g_tval[row + HID + 2 * t];
        n1 = g_tval[row + HID + 2 * t + 1];
    }
    __nv_bfloat162 vv = __floats2bfloat162_rn(v0, v1);
    __nv_bfloat162 ss = __floats2bfloat162_rn(n0 - v0, n1 - v1);
    uint2 pk = make_uint2(*reinterpret_cast<unsigned*>(&vv),
                          *reinterpret_cast<unsigned*>(&ss));
    reinterpret_cast<uint2*>(g_tblb)[((size_t)(it * TBL + j) * 64) + t] = pk;
}

// ---------------- gather: warp per node ----------------
__global__ void gather(const uint4* __restrict__ tbl) {
    int n = (blockIdx.x * blockDim.x + threadIdx.x) >> 5;
    if (n >= NUM_NODES) return;
    int lane = threadIdx.x & 31;
    int beg = __ldg(&g_off[n]);
    int end = __ldg(&g_off[n + 1]);
    float4 acc = f4z();
#pragma unroll 4
    for (int e = beg; e < end; e++) {
        int2 p = __ldg(&g_esrc[e]);
        float t = __int_as_float(p.y);
        int bin = (int)t;
        float f = t - (float)bin;
        uint4 tv = __ldg(tbl + (size_t)bin * 32 + lane);
        float2 v01 = __bfloat1622float2(*reinterpret_cast<__nv_bfloat162*>(&tv.x));
        float2 s01 = __bfloat1622float2(*reinterpret_cast<__nv_bfloat162*>(&tv.y));
        float2 v23 = __bfloat1622float2(*reinterpret_cast<__nv_bfloat162*>(&tv.z));
        float2 s23 = __bfloat1622float2(*reinterpret_cast<__nv_bfloat162*>(&tv.w));
        uint2 xb = __ldcs(reinterpret_cast<const uint2*>(g_xb + (size_t)p.x * HID) + lane);
        float2 x01 = __bfloat1622float2(*reinterpret_cast<__nv_bfloat162*>(&xb.x));
        float2 x23 = __bfloat1622float2(*reinterpret_cast<__nv_bfloat162*>(&xb.y));
        acc.x = fmaf(x01.x, fmaf(f, s01.x, v01.x), acc.x);
        acc.y = fmaf(x01.y, fmaf(f, s01.y, v01.y), acc.y);
        acc.z = fmaf(x23.x, fmaf(f, s23.x, v23.x), acc.z);
        acc.w = fmaf(x23.y, fmaf(f, s23.y, v23.y), acc.w);
    }
    *reinterpret_cast<float4*>(g_agg + (size_t)n * HID + lane * 4) = acc;
}

// ---------------- readout ----------------
__global__ void head_kernel(const float* __restrict__ hw1, const float* __restrict__ hb1,
                            const float* __restrict__ hw2, const float* __restrict__ hb2,
                            const int* __restrict__ batch) {
    int n = (blockIdx.x * blockDim.x + threadIdx.x) >> 5;
    if (n >= NUM_NODES) return;
    int lane = threadIdx.x & 31;
    const float* hrow = g_h + (size_t)n * HID;
    float hr[4];
#pragma unroll
    for (int q = 0; q < 4; q++) hr[q] = hrow[q * 32 + lane];
    float u0 = hb1[lane];
    float u1 = hb1[lane + 32];
#pragma unroll
    for (int k = 0; k < HID; k++) {
        float hv = __shfl_sync(0xffffffffu, hr[k >> 5], k & 31);
        u0 = fmaf(hv, hw1[k * 64 + lane], u0);
        u1 = fmaf(hv, hw1[k * 64 + lane + 32], u1);
    }
    float part = sspf(u0) * hw2[lane] + sspf(u1) * hw2[lane + 32];
#pragma unroll
    for (int o = 16; o; o >>= 1) part += __shfl_down_sync(0xffffffffu, part, o);
    if (lane == 0) {
        int b = batch[n];
        atomicAdd(&g_sums[b], part + hb2[0]);
        atomicAdd(&g_cnts[b], 1.0f);
    }
}

__global__ void finalize(float* __restrict__ out) {
    int g = threadIdx.x;
    if (g < NUM_GRAPHS) out[g] = g_sums[g] / fmaxf(g_cnts[g], 1.0f);
}

// ---------------- launcher ----------------
extern "C" void kernel_launch(void* const* d_in, const int* in_sizes, int n_in,
                              void* d_out, int out_size) {
    const float* pos    = (const float*)d_in[0];
    const float* shift  = (const float*)d_in[1];
    const float* emb    = (const float*)d_in[2];
    const float* mlp_w1 = (const float*)d_in[3];
    const float* mlp_b1 = (const float*)d_in[4];
    const float* mlp_w2 = (const float*)d_in[5];
    const float* mlp_b2 = (const float*)d_in[6];
    const float* cf_w1  = (const float*)d_in[7];
    const float* cf_w2  = (const float*)d_in[8];
    const float* cf_b2  = (const float*)d_in[9];
    const float* lin_w  = (const float*)d_in[10];
    const float* lin_b  = (const float*)d_in[11];
    const float* hw1    = (const float*)d_in[12];
    const float* hb1    = (const float*)d_in[13];
    const float* hw2    = (const float*)d_in[14];
    const float* hb2    = (const float*)d_in[15];
    const int*   z      = (const int*)d_in[16];
    const int*   ei     = (const int*)d_in[17];
    const int*   batch  = (const int*)d_in[18];
    float* out = (float*)d_out;

    uint4* tblb_p;
    cudaGetSymbolAddress((void**)&tblb_p, g_tblb);

    cudaFuncSetAttribute(gemm_xb,        cudaFuncAttributeMaxDynamicSharedMemorySize, SMEM_MMA);
    cudaFuncSetAttribute(node_update<0>, cudaFuncAttributeMaxDynamicSharedMemorySize, SMEM_MMA);
    cudaFuncSetAttribute(node_update<1>, cudaFuncAttributeMaxDynamicSharedMemorySize, SMEM_MMA);

    int gblk = (NUM_NODES + TM - 1) / TM;   // 782
    int sgrid = (SCAN_N + 1023) / 1024;
    dim3 tgrid(TBL, NUM_INTER);

    // ---- stream fork: side stream does weight/table/GEMM path, legacy does edges ----
    // Streams/events are intentionally NOT destroyed: a forked stream may not be
    // destroyed while graph capture is active. kernel_launch is invoked only a
    // couple of times (correctness + capture); the leak is a few host objects.
    cudaStream_t sG;
    cudaStreamCreateWithFlags(&sG, cudaStreamNonBlocking);
    cudaEvent_t eF, eG;
    cudaEventCreateWithFlags(&eF, cudaEventDisableTiming);
    cudaEventCreateWithFlags(&eG, cudaEventDisableTiming);

    cudaEventRecord(eF, 0);                  // fork point on (capturing) legacy stream
    cudaStreamWaitEvent(sG, eF, 0);

    // side stream: weight images -> first GEMM -> Wf table
    prep_w<<<9, 256, 0, sG>>>(cf_w1, cf_w2, lin_w);
    gemm_xb<<<296, 256, SMEM_MMA, sG>>>(emb, z);
    build_val<<<tgrid, 128, 0, sG>>>(mlp_w1, mlp_b1, mlp_w2, mlp_b2);
    build_pack<<<tgrid, 64, 0, sG>>>();
    cudaEventRecord(eG, sG);

    // legacy stream: edge pipeline (independent of side stream)
    zero_meta<<<sgrid, 1024>>>();
    prep_pos4<<<(NUM_NODES + 255) / 256, 256>>>(pos);
    prep_edges<<<(NUM_EDGES + 255) / 256, 256>>>(shift, ei);
    scan_block<<<sgrid, 1024>>>();
    scan_part<<<1, 1024>>>();
    scan_add<<<sgrid, 1024>>>();
    scatter_csr<<<(NUM_EDGES + 255) / 256, 256>>>();

    cudaStreamWaitEvent(0, eG, 0);           // join before gather loop

    int wgrid = (int)(((long long)NUM_NODES * 32 + 255) / 256);
    for (int i = 0; i < NUM_INTER; i++) {
        gather<<<wgrid, 256>>>(tblb_p + (size_t)i * TBL * 32);
        const float* b2p = cf_b2 + (size_t)i * HID;
        const float* bLp = lin_b + (size_t)i * HID;
        if (i < NUM_INTER - 1) {
            node_update<0><<<gblk, 256, SMEM_MMA>>>(3 + i, 6 + i, i + 1, b2p, bLp);
        } else {
            node_update<1><<<gblk, 256, SMEM_MMA>>>(3 + i, 6 + i, 0, b2p, bLp);
        }
    }

    head_kernel<<<wgrid, 256>>>(hw1, hb1, hw2, hb2, batch);
    finalize<<<1, 128>>>(out);
}

// round 17
// speedup vs baseline: 1.1113x; 1.0231x over previous
#include <cuda_runtime.h>
#include <cuda_bf16.h>
#include <math.h>
#include <stdint.h>

#define NUM_NODES 50000
#define NUM_EDGES 1600000
#define NUM_GRAPHS 128
#define HID 128
#define NUM_G 50
#define NUM_INTER 3
#define TBL 1024
#define WTOP 10.0f
#define WCUT 9.6f
#define LOG2F_ 0.6931471805599453f
#define PI_OVER_8 0.39269908169872414f
#define GCOEFF (-18.7578125f)
#define SCAN_N (NUM_NODES + 1)
#define SST 136
#define TM 64
#define TILE_U4 (128 * 17)
#define NT64 ((NUM_NODES + 63) / 64)

typedef unsigned long long u64;
typedef __nv_bfloat16 bf16;

// ---------------- static scratch ----------------
__device__ float  g_tval[NUM_INTER * TBL * HID];
__device__ uint4  g_tblb[NUM_INTER * TBL * 32];
__device__ uint4  g_wimg[9 * 2 * TILE_U4];
__device__ float4 g_pos4[NUM_NODES];
__device__ float  g_h[NUM_NODES * HID];
__device__ bf16   g_xb[NUM_NODES * HID];
__device__ float  g_agg[NUM_NODES * HID];
__device__ int4   g_epack[NUM_EDGES];
__device__ int2   g_esrc[NUM_EDGES];
__device__ int    g_deg[SCAN_N];
__device__ int    g_off[SCAN_N];
__device__ int    g_cur[NUM_NODES];
__device__ int    g_part[64];
__device__ float  g_sums[NUM_GRAPHS];
__device__ float  g_cnts[NUM_GRAPHS];

__device__ __forceinline__ float sspf(float v) {
    float sp = (v > 20.0f) ? v : log1pf(__expf(v));
    return sp - LOG2F_;
}
__device__ __forceinline__ float4 f4z() { return make_float4(0.f, 0.f, 0.f, 0.f); }

// ---------------- cp.async ----------------
#define CP_ASYNC16(saddr, gptr) \
    asm volatile("cp.async.ca.shared.global [%0], [%1], 16;" :: "r"(saddr), "l"(gptr) : "memory")
#define CP_COMMIT() asm volatile("cp.async.commit_group;" ::: "memory")
#define CP_WAIT(n)  asm volatile("cp.async.wait_group %0;" :: "n"(n) : "memory")

// ---------------- MMA smem ----------------
struct SmemMMA {
    bf16 Ah[TM * SST];
    bf16 Al[TM * SST];
    bf16 Wh[128 * SST];
    bf16 Wl[128 * SST];
};
#define SMEM_MMA ((int)sizeof(SmemMMA))

__device__ __forceinline__ unsigned sptr(const void* p) {
    return (unsigned)__cvta_generic_to_shared(p);
}
__device__ __forceinline__ void ldsm4(uint32_t* r, unsigned addr) {
    asm volatile("ldmatrix.sync.aligned.m8n8.x4.shared.b16 {%0,%1,%2,%3}, [%4];"
                 : "=r"(r[0]), "=r"(r[1]), "=r"(r[2]), "=r"(r[3]) : "r"(addr));
}
__device__ __forceinline__ void ldsm4t(uint32_t* r, unsigned addr) {
    asm volatile("ldmatrix.sync.aligned.m8n8.x4.trans.shared.b16 {%0,%1,%2,%3}, [%4];"
                 : "=r"(r[0]), "=r"(r[1]), "=r"(r[2]), "=r"(r[3]) : "r"(addr));
}
__device__ __forceinline__ void mma16816(float* c, const uint32_t* a, uint32_t b0, uint32_t b1) {
    asm volatile("mma.sync.aligned.m16n8k16.row.col.f32.bf16.bf16.f32 "
                 "{%0,%1,%2,%3}, {%4,%5,%6,%7}, {%8,%9}, {%0,%1,%2,%3};"
                 : "+f"(c[0]), "+f"(c[1]), "+f"(c[2]), "+f"(c[3])
                 : "r"(a[0]), "r"(a[1]), "r"(a[2]), "r"(a[3]), "r"(b0), "r"(b1));
}

__device__ __forceinline__ void split_store(bf16* Ah, bf16* Al, int idx, float v0, float v1) {
    bf16 h0 = __float2bfloat16(v0), h1 = __float2bfloat16(v1);
    bf16 l0 = __float2bfloat16(v0 - __bfloat162float(h0));
    bf16 l1 = __float2bfloat16(v1 - __bfloat162float(h1));
    *reinterpret_cast<__nv_bfloat162*>(Ah + idx) = __halves2bfloat162(h0, h1);
    *reinterpret_cast<__nv_bfloat162*>(Al + idx) = __halves2bfloat162(l0, l1);
}

// 256-thread A staging (gemm_xb)
__device__ __forceinline__ void load_splitA256(const float* __restrict__ Ag, int row0,
                                               bf16* Ah, bf16* Al, int tid) {
    int r = tid >> 2, c0 = (tid & 3) * 32;
    bool ok = (row0 + r) < NUM_NODES;
    const float4* src = reinterpret_cast<const float4*>(Ag + (size_t)(row0 + r) * HID + c0);
#pragma unroll
    for (int q = 0; q < 8; q++) {
        float4 v = ok ? __ldg(src + q) : f4z();
        int base = r * SST + c0 + q * 4;
        split_store(Ah, Al, base, v.x, v.y);
        split_store(Ah, Al, base + 2, v.z, v.w);
    }
}

// 512-thread A staging (node_update)
__device__ __forceinline__ void load_splitA512(const float* __restrict__ Ag, int row0,
                                               bf16* Ah, bf16* Al, int tid) {
    int r = tid >> 3, c0 = (tid & 7) * 16;
    bool ok = (row0 + r) < NUM_NODES;
    const float4* src = reinterpret_cast<const float4*>(Ag + (size_t)(row0 + r) * HID + c0);
#pragma unroll
    for (int q = 0; q < 4; q++) {
        float4 v = ok ? __ldg(src + q) : f4z();
        int base = r * SST + c0 + q * 4;
        split_store(Ah, Al, base, v.x, v.y);
        split_store(Ah, Al, base + 2, v.z, v.w);
    }
}

__device__ __forceinline__ void cp_w256(bf16* Wh, bf16* Wl, const uint4* imgh, const uint4* imgl, int tid) {
#pragma unroll
    for (int i = 0; i < 8; i++) {
        int c = tid + i * 256;
        int r = c >> 4, g = c & 15;
        CP_ASYNC16(sptr(Wh + r * SST + g * 8), imgh + r * 17 + g);
        CP_ASYNC16(sptr(Wl + r * SST + g * 8), imgl + r * 17 + g);
    }
}

__device__ __forceinline__ void cp_w512(bf16* Wh, bf16* Wl, const uint4* imgh, const uint4* imgl, int tid) {
#pragma unroll
    for (int i = 0; i < 4; i++) {
        int c = tid + i * 512;
        int r = c >> 4, g = c & 15;
        CP_ASYNC16(sptr(Wh + r * SST + g * 8), imgh + r * 17 + g);
        CP_ASYNC16(sptr(Wl + r * SST + g * 8), imgl + r * 17 + g);
    }
}

// 256-thread mma: warp = 32 rows x 32 cols (gemm_xb)
__device__ __forceinline__ void mma_all(const bf16* Ah, const bf16* Al,
                                        const bf16* Wh, const bf16* Wl,
                                        float acc[2][4][4], int lane, int mb, int nb) {
#pragma unroll
    for (int mt = 0; mt < 2; mt++)
#pragma unroll
        for (int nt = 0; nt < 4; nt++)
#pragma unroll
            for (int q = 0; q < 4; q++) acc[mt][nt][q] = 0.f;

    int l15 = lane & 15, lq = (lane >> 4) * 8;
    int arow = mb * 32 + l15;
#pragma unroll
    for (int kc = 0; kc < 8; kc++) {
        uint32_t ah[2][4], al[2][4];
        ldsm4(ah[0], sptr(Ah + arow * SST + kc * 16 + lq));
        ldsm4(ah[1], sptr(Ah + (arow + 16) * SST + kc * 16 + lq));
        ldsm4(al[0], sptr(Al + arow * SST + kc * 16 + lq));
        ldsm4(al[1], sptr(Al + (arow + 16) * SST + kc * 16 + lq));
#pragma unroll
        for (int ntg = 0; ntg < 2; ntg++) {
            uint32_t bh[4], bl[4];
            unsigned wsoff = (kc * 16 + l15) * SST + nb * 32 + ntg * 16 + lq;
            ldsm4t(bh, sptr(Wh + wsoff));
            ldsm4t(bl, sptr(Wl + wsoff));
            float* c0 = acc[0][ntg * 2];
            float* c1 = acc[0][ntg * 2 + 1];
            float* c2 = acc[1][ntg * 2];
            float* c3 = acc[1][ntg * 2 + 1];
            mma16816(c0, ah[0], bh[0], bh[1]); mma16816(c1, ah[0], bh[2], bh[3]);
            mma16816(c2, ah[1], bh[0], bh[1]); mma16816(c3, ah[1], bh[2], bh[3]);
            mma16816(c0, al[0], bh[0], bh[1]); mma16816(c1, al[0], bh[2], bh[3]);
            mma16816(c2, al[1], bh[0], bh[1]); mma16816(c3, al[1], bh[2], bh[3]);
            mma16816(c0, ah[0], bl[0], bl[1]); mma16816(c1, ah[0], bl[2], bl[3]);
            mma16816(c2, ah[1], bl[0], bl[1]); mma16816(c3, ah[1], bl[2], bl[3]);
        }
    }
}

// 512-thread mma: warp = 32 rows x 16 cols (node_update); mb in {0,1}, nb in {0..7}
__device__ __forceinline__ void mma512(const bf16* Ah, const bf16* Al,
                                       const bf16* Wh, const bf16* Wl,
                                       float acc[2][2][4], int lane, int mb, int nb) {
#pragma unroll
    for (int mt = 0; mt < 2; mt++)
#pragma unroll
        for (int nt = 0; nt < 2; nt++)
#pragma unroll
            for (int q = 0; q < 4; q++) acc[mt][nt][q] = 0.f;

    int l15 = lane & 15, lq = (lane >> 4) * 8;
    int arow = mb * 32 + l15;
#pragma unroll
    for (int kc = 0; kc < 8; kc++) {
        uint32_t ah[2][4], al[2][4];
        ldsm4(ah[0], sptr(Ah + arow * SST + kc * 16 + lq));
        ldsm4(ah[1], sptr(Ah + (arow + 16) * SST + kc * 16 + lq));
        ldsm4(al[0], sptr(Al + arow * SST + kc * 16 + lq));
        ldsm4(al[1], sptr(Al + (arow + 16) * SST + kc * 16 + lq));
        uint32_t bh[4], bl[4];
        unsigned wsoff = (kc * 16 + l15) * SST + nb * 16 + lq;
        ldsm4t(bh, sptr(Wh + wsoff));
        ldsm4t(bl, sptr(Wl + wsoff));
        float* c0 = acc[0][0];
        float* c1 = acc[0][1];
        float* c2 = acc[1][0];
        float* c3 = acc[1][1];
        mma16816(c0, ah[0], bh[0], bh[1]); mma16816(c1, ah[0], bh[2], bh[3]);
        mma16816(c2, ah[1], bh[0], bh[1]); mma16816(c3, ah[1], bh[2], bh[3]);
        mma16816(c0, al[0], bh[0], bh[1]); mma16816(c1, al[0], bh[2], bh[3]);
        mma16816(c2, al[1], bh[0], bh[1]); mma16816(c3, al[1], bh[2], bh[3]);
        mma16816(c0, ah[0], bl[0], bl[1]); mma16816(c1, ah[0], bl[2], bl[3]);
        mma16816(c2, ah[1], bl[0], bl[1]); mma16816(c3, ah[1], bl[2], bl[3]);
    }
}

__device__ __forceinline__ void epi_store_xb256(float acc[2][4][4], int lane, int mb, int nb, int row0) {
#pragma unroll
    for (int mt = 0; mt < 2; mt++) {
        int rl = mb * 32 + mt * 16 + (lane >> 2);
#pragma unroll
        for (int nt = 0; nt < 4; nt++) {
            int col = nb * 32 + nt * 8 + (lane & 3) * 2;
            int r0 = row0 + rl, r1 = r0 + 8;
            if (r0 < NUM_NODES)
                *reinterpret_cast<__nv_bfloat162*>(g_xb + (size_t)r0 * HID + col) =
                    __floats2bfloat162_rn(acc[mt][nt][0], acc[mt][nt][1]);
            if (r1 < NUM_NODES)
                *reinterpret_cast<__nv_bfloat162*>(g_xb + (size_t)r1 * HID + col) =
                    __floats2bfloat162_rn(acc[mt][nt][2], acc[mt][nt][3]);
        }
    }
}

// ---------------- weight image prep ----------------
__global__ void prep_w(const float* __restrict__ cf_w1,
                       const float* __restrict__ cf_w2,
                       const float* __restrict__ lin_w) {
    int m = blockIdx.x;
    const float* W = (m < 3) ? cf_w1 + (size_t)m * HID * HID
                   : (m < 6) ? cf_w2 + (size_t)(m - 3) * HID * HID
                             : lin_w + (size_t)(m - 6) * HID * HID;
    uint4* imgh = g_wimg + (size_t)m * 2 * TILE_U4;
    uint4* imgl = imgh + TILE_U4;
    int tid = threadIdx.x;
#pragma unroll
    for (int i = 0; i < 8; i++) {
        int c = tid + i * 256;
        int r = c >> 4, g = c & 15;
        const float4* src = reinterpret_cast<const float4*>(W + (size_t)r * HID + g * 8);
        float4 v0 = __ldg(src), v1 = __ldg(src + 1);
        float vv[8] = {v0.x, v0.y, v0.z, v0.w, v1.x, v1.y, v1.z, v1.w};
        unsigned ph[4], pl[4];
#pragma unroll
        for (int e = 0; e < 4; e++) {
            bf16 h0 = __float2bfloat16(vv[2 * e]);
            bf16 h1 = __float2bfloat16(vv[2 * e + 1]);
            bf16 l0 = __float2bfloat16(vv[2 * e] - __bfloat162float(h0));
            bf16 l1 = __float2bfloat16(vv[2 * e + 1] - __bfloat162float(h1));
            __nv_bfloat162 hp = __halves2bfloat162(h0, h1);
            __nv_bfloat162 lp = __halves2bfloat162(l0, l1);
            ph[e] = *reinterpret_cast<unsigned*>(&hp);
            pl[e] = *reinterpret_cast<unsigned*>(&lp);
        }
        imgh[r * 17 + g] = make_uint4(ph[0], ph[1], ph[2], ph[3]);
        imgl[r * 17 + g] = make_uint4(pl[0], pl[1], pl[2], pl[3]);
    }
}

// ---------------- persistent init + first GEMM (TM=64, 256 thr, 2 CTA/SM, grid 296) ----------------
__global__ void __launch_bounds__(256, 2) gemm_xb(const float* __restrict__ emb,
                                                  const int* __restrict__ z) {
    extern __shared__ char smraw[];
    SmemMMA& sm = *reinterpret_cast<SmemMMA*>(smraw);
    int tid = threadIdx.x, lane = tid & 31, wid = tid >> 5;
    int mb = wid & 1, nb = wid >> 1;

    cp_w256(sm.Wh, sm.Wl, g_wimg, g_wimg + TILE_U4, tid);
    CP_COMMIT();

    int t = blockIdx.x;
    if (t < NT64) {
        int row0 = t * TM;
        int r = tid >> 2, c0 = (tid & 3) * 32;
        int gr = row0 + r;
        bool ok = gr < NUM_NODES;
        int zz = ok ? __ldg(z + gr) : 0;
        const float4* src = reinterpret_cast<const float4*>(emb + (size_t)zz * HID + c0);
        float4* hdst = reinterpret_cast<float4*>(g_h + (size_t)gr * HID + c0);
#pragma unroll
        for (int q = 0; q < 8; q++) {
            float4 v = ok ? __ldg(src + q) : f4z();
            if (ok) hdst[q] = v;
            int base = r * SST + c0 + q * 4;
            split_store(sm.Ah, sm.Al, base, v.x, v.y);
            split_store(sm.Ah, sm.Al, base + 2, v.z, v.w);
        }
    }
    CP_WAIT(0);
    __syncthreads();

    while (t < NT64) {
        int row0 = t * TM;
        float acc[2][4][4];
        mma_all(sm.Ah, sm.Al, sm.Wh, sm.Wl, acc, lane, mb, nb);
        epi_store_xb256(acc, lane, mb, nb, row0);
        int tn = t + gridDim.x;
        __syncthreads();
        if (tn < NT64) {
            int row0n = tn * TM;
            int r = tid >> 2, c0 = (tid & 3) * 32;
            int gr = row0n + r;
            bool ok = gr < NUM_NODES;
            int zz = ok ? __ldg(z + gr) : 0;
            const float4* src = reinterpret_cast<const float4*>(emb + (size_t)zz * HID + c0);
            float4* hdst = reinterpret_cast<float4*>(g_h + (size_t)gr * HID + c0);
#pragma unroll
            for (int q = 0; q < 8; q++) {
                float4 v = ok ? __ldg(src + q) : f4z();
                if (ok) hdst[q] = v;
                int base = r * SST + c0 + q * 4;
                split_store(sm.Ah, sm.Al, base, v.x, v.y);
                split_store(sm.Ah, sm.Al, base + 2, v.z, v.w);
            }
            __syncthreads();
        }
        t = tn;
    }
}

// ---------------- fused node update (TM=64, 512 thr, 2 CTA/SM) ----------------
template <int LAST>
__global__ void __launch_bounds__(512, 2) node_update(int mW2, int mWL, int mW1n,
                                                      const float* __restrict__ b2,
                                                      const float* __restrict__ bL) {
    extern __shared__ char smraw[];
    SmemMMA& sm = *reinterpret_cast<SmemMMA*>(smraw);
    int tid = threadIdx.x, lane = tid & 31, wid = tid >> 5;   // wid 0..15
    int mb = wid & 1, nb = wid >> 1;                          // nb 0..7
    int row0 = blockIdx.x * TM;
    float acc[2][2][4];

    const uint4* i2 = g_wimg + (size_t)mW2 * 2 * TILE_U4;
    cp_w512(sm.Wh, sm.Wl, i2, i2 + TILE_U4, tid);
    CP_COMMIT();
    load_splitA512(g_agg, row0, sm.Ah, sm.Al, tid);
    CP_WAIT(0);
    __syncthreads();

    // ---- pass A: agg @ W2 ----
    mma512(sm.Ah, sm.Al, sm.Wh, sm.Wl, acc, lane, mb, nb);
    __syncthreads();

    const uint4* iL = g_wimg + (size_t)mWL * 2 * TILE_U4;
    cp_w512(sm.Wh, sm.Wl, iL, iL + TILE_U4, tid);
    CP_COMMIT();

    // epilogue A: Us = ssp(D + b2) -> Ah/Al
#pragma unroll
    for (int mt = 0; mt < 2; mt++) {
        int rl = mb * 32 + mt * 16 + (lane >> 2);
#pragma unroll
        for (int nt = 0; nt < 2; nt++) {
            int col = nb * 16 + nt * 8 + (lane & 3) * 2;
            float bb0 = __ldg(b2 + col), bb1 = __ldg(b2 + col + 1);
            split_store(sm.Ah, sm.Al, rl * SST + col,
                        sspf(acc[mt][nt][0] + bb0), sspf(acc[mt][nt][1] + bb1));
            split_store(sm.Ah, sm.Al, (rl + 8) * SST + col,
                        sspf(acc[mt][nt][2] + bb0), sspf(acc[mt][nt][3] + bb1));
        }
    }
    CP_WAIT(0);
    __syncthreads();

    // ---- pass B: Us @ WL ----
    mma512(sm.Ah, sm.Al, sm.Wh, sm.Wl, acc, lane, mb, nb);
    __syncthreads();

    if (!LAST) {
        const uint4* iN = g_wimg + (size_t)mW1n * 2 * TILE_U4;
        cp_w512(sm.Wh, sm.Wl, iN, iN + TILE_U4, tid);
        CP_COMMIT();
    }

    // epilogue B: h += D + bL ; stage h_new into Ah/Al
#pragma unroll
    for (int mt = 0; mt < 2; mt++) {
        int rl = mb * 32 + mt * 16 + (lane >> 2);
#pragma unroll
        for (int nt = 0; nt < 2; nt++) {
            int col = nb * 16 + nt * 8 + (lane & 3) * 2;
            float bb0 = __ldg(bL + col), bb1 = __ldg(bL + col + 1);
#pragma unroll
            for (int half = 0; half < 2; half++) {
                int r = row0 + rl + half * 8;
                bool ok = r < NUM_NODES;
                float2 hv = ok ? *reinterpret_cast<const float2*>(g_h + (size_t)r * HID + col)
                               : make_float2(0.f, 0.f);
                float v0 = hv.x + acc[mt][nt][half * 2] + bb0;
                float v1 = hv.y + acc[mt][nt][half * 2 + 1] + bb1;
                if (ok)
                    *reinterpret_cast<float2*>(g_h + (size_t)r * HID + col) = make_float2(v0, v1);
                if (!LAST)
                    split_store(sm.Ah, sm.Al, (rl + half * 8) * SST + col, v0, v1);
            }
        }
    }
    if (LAST) return;

    CP_WAIT(0);
    __syncthreads();

    // ---- pass C: xb = h_new @ W1n ----
    mma512(sm.Ah, sm.Al, sm.Wh, sm.Wl, acc, lane, mb, nb);
#pragma unroll
    for (int mt = 0; mt < 2; mt++) {
        int rl = mb * 32 + mt * 16 + (lane >> 2);
#pragma unroll
        for (int nt = 0; nt < 2; nt++) {
            int col = nb * 16 + nt * 8 + (lane & 3) * 2;
            int r0 = row0 + rl, r1 = r0 + 8;
            if (r0 < NUM_NODES)
                *reinterpret_cast<__nv_bfloat162*>(g_xb + (size_t)r0 * HID + col) =
                    __floats2bfloat162_rn(acc[mt][nt][0], acc[mt][nt][1]);
            if (r1 < NUM_NODES)
                *reinterpret_cast<__nv_bfloat162*>(g_xb + (size_t)r1 * HID + col) =
                    __floats2bfloat162_rn(acc[mt][nt][2], acc[mt][nt][3]);
        }
    }
}

// ---------------- setup kernels ----------------
__global__ void zero_meta() {
    int i = blockIdx.x * blockDim.x + threadIdx.x;
    if (i < SCAN_N) g_deg[i] = 0;
}

__global__ void prep_pos4(const float* __restrict__ pos) {
    int n = blockIdx.x * blockDim.x + threadIdx.x;
    if (n >= NUM_NODES) return;
    g_pos4[n] = make_float4(__ldg(pos + n * 3), __ldg(pos + n * 3 + 1),
                            __ldg(pos + n * 3 + 2), 0.f);
}

__global__ void prep_edges(const float* __restrict__ shift,
                           const int* __restrict__ ei) {
    int e = blockIdx.x * blockDim.x + threadIdx.x;
    if (e >= NUM_EDGES) return;
    int s = __ldg(ei + e);
    int d = __ldg(ei + NUM_EDGES + e);
    float4 ps = __ldg(&g_pos4[s]);
    float4 pd = __ldg(&g_pos4[d]);
    float sx = __ldg(shift + e * 3 + 0);
    float sy = __ldg(shift + e * 3 + 1);
    float sz = __ldg(shift + e * 3 + 2);
    float dx = ps.x - pd.x - sx;
    float dy = ps.y - pd.y - sy;
    float dz = ps.z - pd.z - sz;
    float w = sqrtf(dx * dx + dy * dy + dz * dz);
    float t = -1.0f;
    if (w < WCUT) {
        t = w * ((float)(TBL - 1) / WTOP);
        atomicAdd(&g_deg[d + 1], 1);
    }
    g_epack[e] = make_int4(s, d, __float_as_int(t), 0);
}

__device__ __forceinline__ int blk_incl_scan(int v, int tid, int* warp_sums) {
    int x = v;
#pragma unroll
    for (int o = 1; o < 32; o <<= 1) {
        int y = __shfl_up_sync(0xffffffffu, x, o);
        if ((tid & 31) >= o) x += y;
    }
    if ((tid & 31) == 31) warp_sums[tid >> 5] = x;
    __syncthreads();
    if (tid < 32) {
        int s = warp_sums[tid];
#pragma unroll
        for (int o = 1; o < 32; o <<= 1) {
            int y = __shfl_up_sync(0xffffffffu, s, o);
            if (tid >= o) s += y;
        }
        warp_sums[tid] = s;
    }
    __syncthreads();
    return x + ((tid >= 32) ? warp_sums[(tid >> 5) - 1] : 0);
}

__global__ void scan_block() {
    __shared__ int ws[32];
    int tid = threadIdx.x;
    int gid = blockIdx.x * 1024 + tid;
    int v = (gid < SCAN_N) ? g_deg[gid] : 0;
    int incl = blk_incl_scan(v, tid, ws);
    if (gid < SCAN_N) g_off[gid] = incl;
    if (tid == 1023) g_part[blockIdx.x] = incl;
}

__global__ void scan_part() {
    __shared__ int ws[32];
    int tid = threadIdx.x;
    int v = (tid < 49) ? g_part[tid] : 0;
    int incl = blk_incl_scan(v, tid, ws);
    if (tid < 64) g_part[tid] = incl - v;
    if (tid < NUM_GRAPHS) { g_sums[tid] = 0.f; g_cnts[tid] = 0.f; }
}

__global__ void scan_add() {
    int tid = threadIdx.x;
    int gid = blockIdx.x * 1024 + tid;
    if (gid >= SCAN_N) return;
    int val = g_off[gid] + g_part[blockIdx.x];
    g_off[gid] = val;
    if (gid < NUM_NODES) g_cur[gid] = val;
}

__global__ void scatter_csr() {
    int e = blockIdx.x * blockDim.x + threadIdx.x;
    if (e >= NUM_EDGES) return;
    int4 pk = __ldg(&g_epack[e]);
    if (__int_as_float(pk.z) < 0.f) return;
    int pos = atomicAdd(&g_cur[pk.y], 1);
    g_esrc[pos] = make_int2(pk.x, pk.z);
}

// ---------------- Wf(w) table ----------------
__global__ void build_val(const float* __restrict__ w1, const float* __restrict__ b1,
                          const float* __restrict__ w2, const float* __restrict__ b2) {
    int j = blockIdx.x, it = blockIdx.y, tid = threadIdx.x;
    __shared__ float attr[NUM_G];
    __shared__ float act[HID];
    float w = (float)j * (WTOP / (float)(TBL - 1));
    if (tid < NUM_G) {
        float off = (float)tid * (8.0f / 49.0f);
        float dlt = w - off;
        attr[tid] = __expf(GCOEFF * dlt * dlt);
    }
    __syncthreads();
    const float* W1 = w1 + it * NUM_G * HID;
    float u = b1[it * HID + tid];
#pragma unroll
    for (int g = 0; g < NUM_G; g++) u += attr[g] * W1[g * HID + tid];
    act[tid] = sspf(u);
    __syncthreads();
    const float* W2 = w2 + it * HID * HID;
    float v = b2[it * HID + tid];
#pragma unroll 8
    for (int k = 0; k < HID; k++) v += act[k] * W2[k * HID + tid];
    float C = 0.5f * (cosf(w * PI_OVER_8) + 1.0f);
    g_tval[(size_t)(it * TBL + j) * HID + tid] = v * C;
}

__global__ void build_pack() {
    int j = blockIdx.x, it = blockIdx.y, t = threadIdx.x;
    size_t row = (size_t)(it * TBL + j) * HID;
    float v0 = g_tval[row + 2 * t];
    float v1 = g_tval[row + 2 * t + 1];
    float n0 = v0, n1 = v1;
    if (j < TBL - 1) {
        n0 = g_tval[row + HID + 2 * t];
        n1 = g_tval[row + HID + 2 * t + 1];
    }
    __nv_bfloat162 vv = __floats2bfloat162_rn(v0, v1);
    __nv_bfloat162 ss = __floats2bfloat162_rn(n0 - v0, n1 - v1);
    uint2 pk = make_uint2(*reinterpret_cast<unsigned*>(&vv),
                          *reinterpret_cast<unsigned*>(&ss));
    reinterpret_cast<uint2*>(g_tblb)[((size_t)(it * TBL + j) * 64) + t] = pk;
}

// ---------------- gather: warp per node ----------------
__global__ void gather(const uint4* __restrict__ tbl) {
    int n = (blockIdx.x * blockDim.x + threadIdx.x) >> 5;
    if (n >= NUM_NODES) return;
    int lane = threadIdx.x & 31;
    int beg = __ldg(&g_off[n]);
    int end = __ldg(&g_off[n + 1]);
    float4 acc = f4z();
#pragma unroll 4
    for (int e = beg; e < end; e++) {
        int2 p = __ldg(&g_esrc[e]);
        float t = __int_as_float(p.y);
        int bin = (int)t;
        float f = t - (float)bin;
        uint4 tv = __ldg(tbl + (size_t)bin * 32 + lane);
        float2 v01 = __bfloat1622float2(*reinterpret_cast<__nv_bfloat162*>(&tv.x));
        float2 s01 = __bfloat1622float2(*reinterpret_cast<__nv_bfloat162*>(&tv.y));
        float2 v23 = __bfloat1622float2(*reinterpret_cast<__nv_bfloat162*>(&tv.z));
        float2 s23 = __bfloat1622float2(*reinterpret_cast<__nv_bfloat162*>(&tv.w));
        uint2 xb = __ldcs(reinterpret_cast<const uint2*>(g_xb + (size_t)p.x * HID) + lane);
        float2 x01 = __bfloat1622float2(*reinterpret_cast<__nv_bfloat162*>(&xb.x));
        float2 x23 = __bfloat1622float2(*reinterpret_cast<__nv_bfloat162*>(&xb.y));
        acc.x = fmaf(x01.x, fmaf(f, s01.x, v01.x), acc.x);
        acc.y = fmaf(x01.y, fmaf(f, s01.y, v01.y), acc.y);
        acc.z = fmaf(x23.x, fmaf(f, s23.x, v23.x), acc.z);
        acc.w = fmaf(x23.y, fmaf(f, s23.y, v23.y), acc.w);
    }
    *reinterpret_cast<float4*>(g_agg + (size_t)n * HID + lane * 4) = acc;
}

// ---------------- readout ----------------
__global__ void head_kernel(const float* __restrict__ hw1, const float* __restrict__ hb1,
                            const float* __restrict__ hw2, const float* __restrict__ hb2,
                            const int* __restrict__ batch) {
    int n = (blockIdx.x * blockDim.x + threadIdx.x) >> 5;
    if (n >= NUM_NODES) return;
    int lane = threadIdx.x & 31;
    const float* hrow = g_h + (size_t)n * HID;
    float hr[4];
#pragma unroll
    for (int q = 0; q < 4; q++) hr[q] = hrow[q * 32 + lane];
    float u0 = hb1[lane];
    float u1 = hb1[lane + 32];
#pragma unroll
    for (int k = 0; k < HID; k++) {
        float hv = __shfl_sync(0xffffffffu, hr[k >> 5], k & 31);
        u0 = fmaf(hv, hw1[k * 64 + lane], u0);
        u1 = fmaf(hv, hw1[k * 64 + lane + 32], u1);
    }
    float part = sspf(u0) * hw2[lane] + sspf(u1) * hw2[lane + 32];
#pragma unroll
    for (int o = 16; o; o >>= 1) part += __shfl_down_sync(0xffffffffu, part, o);
    if (lane == 0) {
        int b = batch[n];
        atomicAdd(&g_sums[b], part + hb2[0]);
        atomicAdd(&g_cnts[b], 1.0f);
    }
}

__global__ void finalize(float* __restrict__ out) {
    int g = threadIdx.x;
    if (g < NUM_GRAPHS) out[g] = g_sums[g] / fmaxf(g_cnts[g], 1.0f);
}

// ---------------- launcher ----------------
extern "C" void kernel_launch(void* const* d_in, const int* in_sizes, int n_in,
                              void* d_out, int out_size) {
    const float* pos    = (const float*)d_in[0];
    const float* shift  = (const float*)d_in[1];
    const float* emb    = (const float*)d_in[2];
    const float* mlp_w1 = (const float*)d_in[3];
    const float* mlp_b1 = (const float*)d_in[4];
    const float* mlp_w2 = (const float*)d_in[5];
    const float* mlp_b2 = (const float*)d_in[6];
    const float* cf_w1  = (const float*)d_in[7];
    const float* cf_w2  = (const float*)d_in[8];
    const float* cf_b2  = (const float*)d_in[9];
    const float* lin_w  = (const float*)d_in[10];
    const float* lin_b  = (const float*)d_in[11];
    const float* hw1    = (const float*)d_in[12];
    const float* hb1    = (const float*)d_in[13];
    const float* hw2    = (const float*)d_in[14];
    const float* hb2    = (const float*)d_in[15];
    const int*   z      = (const int*)d_in[16];
    const int*   ei     = (const int*)d_in[17];
    const int*   batch  = (const int*)d_in[18];
    float* out = (float*)d_out;

    uint4* tblb_p;
    cudaGetSymbolAddress((void**)&tblb_p, g_tblb);

    cudaFuncSetAttribute(gemm_xb,        cudaFuncAttributeMaxDynamicSharedMemorySize, SMEM_MMA);
    cudaFuncSetAttribute(node_update<0>, cudaFuncAttributeMaxDynamicSharedMemorySize, SMEM_MMA);
    cudaFuncSetAttribute(node_update<1>, cudaFuncAttributeMaxDynamicSharedMemorySize, SMEM_MMA);

    int gblk = (NUM_NODES + TM - 1) / TM;   // 782
    int sgrid = (SCAN_N + 1023) / 1024;
    dim3 tgrid(TBL, NUM_INTER);

    // ---- stream fork (R16 win): side stream = weights/GEMM/table, legacy = edges ----
    cudaStream_t sG;
    cudaStreamCreateWithFlags(&sG, cudaStreamNonBlocking);
    cudaEvent_t eF, eG;
    cudaEventCreateWithFlags(&eF, cudaEventDisableTiming);
    cudaEventCreateWithFlags(&eG, cudaEventDisableTiming);

    cudaEventRecord(eF, 0);
    cudaStreamWaitEvent(sG, eF, 0);

    prep_w<<<9, 256, 0, sG>>>(cf_w1, cf_w2, lin_w);
    gemm_xb<<<296, 256, SMEM_MMA, sG>>>(emb, z);
    build_val<<<tgrid, 128, 0, sG>>>(mlp_w1, mlp_b1, mlp_w2, mlp_b2);
    build_pack<<<tgrid, 64, 0, sG>>>();
    cudaEventRecord(eG, sG);

    zero_meta<<<sgrid, 1024>>>();
    prep_pos4<<<(NUM_NODES + 255) / 256, 256>>>(pos);
    prep_edges<<<(NUM_EDGES + 255) / 256, 256>>>(shift, ei);
    scan_block<<<sgrid, 1024>>>();
    scan_part<<<1, 1024>>>();
    scan_add<<<sgrid, 1024>>>();
    scatter_csr<<<(NUM_EDGES + 255) / 256, 256>>>();

    cudaStreamWaitEvent(0, eG, 0);

    int wgrid = (int)(((long long)NUM_NODES * 32 + 255) / 256);
    for (int i = 0; i < NUM_INTER; i++) {
        gather<<<wgrid, 256>>>(tblb_p + (size_t)i * TBL * 32);
        const float* b2p = cf_b2 + (size_t)i * HID;
        const float* bLp = lin_b + (size_t)i * HID;
        if (i < NUM_INTER - 1) {
            node_update<0><<<gblk, 512, SMEM_MMA>>>(3 + i, 6 + i, i + 1, b2p, bLp);
        } else {
            node_update<1><<<gblk, 512, SMEM_MMA>>>(3 + i, 6 + i, 0, b2p, bLp);
        }
    }

    head_kernel<<<wgrid, 256>>>(hw1, hb1, hw2, hb2, batch);
    finalize<<<1, 128>>>(out);
}